// round 4
// baseline (speedup 1.0000x reference)
#include <cuda_runtime.h>

#define NN 10000
#define EE 100000
#define EDGE_BLOCKS ((EE + 63) / 64)
#define NT_BLOCKS ((NN + 63) / 64)
#define W3H_BLOCKS (NT_BLOCKS * 16)

// ---------------- scratch (static device globals; no allocation) ----------------
__device__ float g_h[NN * 32];
__device__ float g_coord[NN * 3];
__device__ float g_k2[(size_t)EE * 128];
__device__ float g_W3h[(size_t)NN * 4096];
__device__ float g_acch[NN * 32];
__device__ float g_accc[NN * 3];
__device__ int   g_cntr[NN];
__device__ int   g_cptr[NN + 1];
__device__ int   g_ebc[EE];

__device__ __forceinline__ unsigned f2tf32(float f) {
    unsigned u;
    asm("cvt.rna.tf32.f32 %0, %1;" : "=r"(u) : "f"(f));
    return u;
}
__device__ __forceinline__ void split_tf32(float x, unsigned& hi, unsigned& lo) {
    hi = f2tf32(x);
    lo = f2tf32(x - __uint_as_float(hi));
}
__device__ __forceinline__ void mma_tf32(float& c0, float& c1, float& c2, float& c3,
                                         unsigned a0, unsigned a1, unsigned a2, unsigned a3,
                                         unsigned b0, unsigned b1) {
    asm("mma.sync.aligned.m16n8k8.row.col.f32.tf32.tf32.f32 "
        "{%0,%1,%2,%3}, {%4,%5,%6,%7}, {%8,%9}, {%0,%1,%2,%3};"
        : "+f"(c0), "+f"(c1), "+f"(c2), "+f"(c3)
        : "r"(a0), "r"(a1), "r"(a2), "r"(a3), "r"(b0), "r"(b1));
}

// ---------------- init ----------------
__global__ void k_prep(const float* __restrict__ x, const float* __restrict__ w,
                       const float* __restrict__ b, const float* __restrict__ ci) {
    int idx = blockIdx.x * blockDim.x + threadIdx.x;
    if (idx < NN * 32) {
        int n = idx >> 5, j = idx & 31;
        float s = b[j];
        s += x[n * 3 + 0] * w[j] + x[n * 3 + 1] * w[32 + j] + x[n * 3 + 2] * w[64 + j];
        g_h[idx] = s;
        g_acch[idx] = 0.f;
    }
    if (idx < NN * 3) { g_coord[idx] = ci[idx]; g_accc[idx] = 0.f; }
    if (idx < NN) g_cntr[idx] = 0;
}

// ---------------- CSR build: hist + scan + scatter in one single-block kernel ----
__global__ __launch_bounds__(1024) void k_csr(const int* __restrict__ ei) {
    __shared__ int scnt[NN];
    __shared__ int ss[1024];
    int t = threadIdx.x;
    for (int i = t; i < NN; i += 1024) scnt[i] = 0;
    __syncthreads();
    for (int e = t; e < EE; e += 1024) {
        atomicAdd(&scnt[ei[EE + e]], 1);
        atomicAdd(&g_cntr[ei[e]], 1);
    }
    __syncthreads();
    int base = t * 10;
    int loc[10];
    int s = 0;
#pragma unroll
    for (int i = 0; i < 10; i++) {
        int v = (base + i < NN) ? scnt[base + i] : 0;
        loc[i] = s; s += v;
    }
    ss[t] = s;
    __syncthreads();
    for (int off = 1; off < 1024; off <<= 1) {
        int v = (t >= off) ? ss[t - off] : 0;
        __syncthreads();
        ss[t] += v;
        __syncthreads();
    }
    int pre = (t > 0) ? ss[t - 1] : 0;
#pragma unroll
    for (int i = 0; i < 10; i++)
        if (base + i < NN) g_cptr[base + i] = pre + loc[i];
    if (t == 1023) g_cptr[NN] = ss[1023];
    __syncthreads();
#pragma unroll
    for (int i = 0; i < 10; i++)
        if (base + i < NN) scnt[base + i] = pre + loc[i];   // running cursor
    __syncthreads();
    for (int e = t; e < EE; e += 1024) {
        int p = atomicAdd(&scnt[ei[EE + e]], 1);
        g_ebc[p] = e;
    }
}

// ---------------- fused edge-MLP + W3h GEMM (heterogeneous grid) -----------------
struct SmemEdge {
    float k1[64][68];
    float w2t[64][68];
    float kin[64][8];
    float w1[7 * 64];
    float b1[64];
    float b2[128];
};
struct SmemW3h {
    float a[64][36];
    float b[256][36];
};

__device__ void edge_part(char* sb, int bid,
                          const int* __restrict__ ei, const float* __restrict__ attr,
                          const float* __restrict__ W1, const float* __restrict__ B1,
                          const float* __restrict__ W2, const float* __restrict__ B2) {
    SmemEdge& sm = *(SmemEdge*)sb;
    int t = threadIdx.x, warp = t >> 5, lane = t & 31;
    int e0 = bid * 64;

    for (int i = t; i < 7 * 64; i += 256) sm.w1[i] = W1[i];
    if (t < 64) sm.b1[t] = B1[t];
    else if (t < 192) sm.b2[t - 64] = B2[t - 64];

    if (t < 64) {
        int e = e0 + t;
        float rad = 0.f;
        if (e < EE) {
            int r = ei[e], c = ei[EE + e];
            float d0 = g_coord[r * 3 + 0] - g_coord[c * 3 + 0];
            float d1 = g_coord[r * 3 + 1] - g_coord[c * 3 + 1];
            float d2 = g_coord[r * 3 + 2] - g_coord[c * 3 + 2];
            rad = d0 * d0 + d1 * d1 + d2 * d2;
#pragma unroll
            for (int q = 0; q < 6; q++) sm.kin[t][q] = attr[e * 6 + q];
        } else {
#pragma unroll
            for (int q = 0; q < 6; q++) sm.kin[t][q] = 0.f;
        }
        sm.kin[t][6] = rad;
    }
    __syncthreads();

    // phase 1: k1[e][c], lanes vary c -> conflict-free
    for (int i = t; i < 64 * 64; i += 256) {
        int c = i & 63, e = i >> 6;
        float s = sm.b1[c];
#pragma unroll
        for (int q = 0; q < 7; q++) s = fmaf(sm.kin[e][q], sm.w1[q * 64 + c], s);
        sm.k1[e][c] = fmaxf(s, 0.f);
    }

    int wm = warp & 3, wn = warp >> 2;
    int qr = lane >> 2, qc = lane & 3;

    for (int half = 0; half < 2; half++) {
        __syncthreads();
        for (int i = t; i < 64 * 64; i += 256) {
            int col = i & 63, k = i >> 6;
            sm.w2t[col][k] = W2[k * 128 + half * 64 + col];
        }
        __syncthreads();

        float acc[4][4];
#pragma unroll
        for (int nt = 0; nt < 4; nt++)
#pragma unroll
            for (int j = 0; j < 4; j++) acc[nt][j] = 0.f;

#pragma unroll
        for (int ks = 0; ks < 8; ks++) {
            int k0 = ks * 8;
            unsigned ah[4], al[4];
            split_tf32(sm.k1[wm * 16 + qr][k0 + qc],     ah[0], al[0]);
            split_tf32(sm.k1[wm * 16 + qr + 8][k0 + qc], ah[1], al[1]);
            split_tf32(sm.k1[wm * 16 + qr][k0 + qc + 4],     ah[2], al[2]);
            split_tf32(sm.k1[wm * 16 + qr + 8][k0 + qc + 4], ah[3], al[3]);
#pragma unroll
            for (int nt = 0; nt < 4; nt++) {
                int cb = wn * 32 + nt * 8;
                unsigned bh0, bl0, bh1, bl1;
                split_tf32(sm.w2t[cb + qr][k0 + qc],     bh0, bl0);
                split_tf32(sm.w2t[cb + qr][k0 + qc + 4], bh1, bl1);
                mma_tf32(acc[nt][0], acc[nt][1], acc[nt][2], acc[nt][3],
                         ah[0], ah[1], ah[2], ah[3], bh0, bh1);
                mma_tf32(acc[nt][0], acc[nt][1], acc[nt][2], acc[nt][3],
                         al[0], al[1], al[2], al[3], bh0, bh1);
                mma_tf32(acc[nt][0], acc[nt][1], acc[nt][2], acc[nt][3],
                         ah[0], ah[1], ah[2], ah[3], bl0, bl1);
            }
        }
        int eA = e0 + wm * 16 + qr, eB = eA + 8;
#pragma unroll
        for (int nt = 0; nt < 4; nt++) {
            int col = half * 64 + wn * 32 + nt * 8 + 2 * qc;
            float bx = sm.b2[col], by = sm.b2[col + 1];
            if (eA < EE)
                *(float2*)&g_k2[(size_t)eA * 128 + col] =
                    make_float2(fmaxf(acc[nt][0] + bx, 0.f), fmaxf(acc[nt][1] + by, 0.f));
            if (eB < EE)
                *(float2*)&g_k2[(size_t)eB * 128 + col] =
                    make_float2(fmaxf(acc[nt][2] + bx, 0.f), fmaxf(acc[nt][3] + by, 0.f));
        }
    }
}

__device__ void w3h_part(char* sb, int bid, const float* __restrict__ W3) {
    SmemW3h& sm = *(SmemW3h*)sb;
    int t = threadIdx.x, warp = t >> 5, lane = t & 31;
    int o0 = (bid & 15) * 256, n0 = (bid >> 4) * 64;

    for (int i = t; i < 64 * 8; i += 256) {
        int n = i >> 3, kq = i & 7;
        float4 v = make_float4(0.f, 0.f, 0.f, 0.f);
        if (n0 + n < NN) v = *(const float4*)&g_h[(n0 + n) * 32 + kq * 4];
        sm.a[n][kq * 4 + 0] = v.x; sm.a[n][kq * 4 + 1] = v.y;
        sm.a[n][kq * 4 + 2] = v.z; sm.a[n][kq * 4 + 3] = v.w;
    }
    for (int i = t; i < 256 * 8; i += 256) {
        int o = i >> 3, kq = i & 7;
        float4 v = *(const float4*)&W3[(size_t)(o0 + o) * 32 + kq * 4];
        sm.b[o][kq * 4 + 0] = v.x; sm.b[o][kq * 4 + 1] = v.y;
        sm.b[o][kq * 4 + 2] = v.z; sm.b[o][kq * 4 + 3] = v.w;
    }
    __syncthreads();

    int wm = warp & 3, wn = warp >> 2;
    int qr = lane >> 2, qc = lane & 3;
    float acc[16][4];
#pragma unroll
    for (int nt = 0; nt < 16; nt++)
#pragma unroll
        for (int j = 0; j < 4; j++) acc[nt][j] = 0.f;

#pragma unroll
    for (int ks = 0; ks < 4; ks++) {
        int k0 = ks * 8;
        unsigned ah[4], al[4];
        split_tf32(sm.a[wm * 16 + qr][k0 + qc],     ah[0], al[0]);
        split_tf32(sm.a[wm * 16 + qr + 8][k0 + qc], ah[1], al[1]);
        split_tf32(sm.a[wm * 16 + qr][k0 + qc + 4],     ah[2], al[2]);
        split_tf32(sm.a[wm * 16 + qr + 8][k0 + qc + 4], ah[3], al[3]);
#pragma unroll
        for (int nt = 0; nt < 16; nt++) {
            int ob = wn * 128 + nt * 8;
            unsigned bh0, bl0, bh1, bl1;
            split_tf32(sm.b[ob + qr][k0 + qc],     bh0, bl0);
            split_tf32(sm.b[ob + qr][k0 + qc + 4], bh1, bl1);
            mma_tf32(acc[nt][0], acc[nt][1], acc[nt][2], acc[nt][3],
                     ah[0], ah[1], ah[2], ah[3], bh0, bh1);
            mma_tf32(acc[nt][0], acc[nt][1], acc[nt][2], acc[nt][3],
                     al[0], al[1], al[2], al[3], bh0, bh1);
            mma_tf32(acc[nt][0], acc[nt][1], acc[nt][2], acc[nt][3],
                     ah[0], ah[1], ah[2], ah[3], bl0, bl1);
        }
    }

    int nA = n0 + wm * 16 + qr, nB = nA + 8;
#pragma unroll
    for (int nt = 0; nt < 16; nt++) {
        int o = o0 + wn * 128 + nt * 8 + 2 * qc;
        if (nA < NN) *(float2*)&g_W3h[(size_t)nA * 4096 + o] = make_float2(acc[nt][0], acc[nt][1]);
        if (nB < NN) *(float2*)&g_W3h[(size_t)nB * 4096 + o] = make_float2(acc[nt][2], acc[nt][3]);
    }
}

__global__ __launch_bounds__(256) void k_edge_w3h(
    const int* __restrict__ ei, const float* __restrict__ attr,
    const float* __restrict__ W1, const float* __restrict__ B1,
    const float* __restrict__ W2, const float* __restrict__ B2,
    const float* __restrict__ W3) {
    constexpr unsigned SBYTES = sizeof(SmemW3h) > sizeof(SmemEdge) ? sizeof(SmemW3h) : sizeof(SmemEdge);
    __shared__ __align__(16) char sb[SBYTES];
    if (blockIdx.x < EDGE_BLOCKS) edge_part(sb, blockIdx.x, ei, attr, W1, B1, W2, B2);
    else                          w3h_part(sb, blockIdx.x - EDGE_BLOCKS, W3);
}

// ---------------- contraction: warp per col-node, W3h row in regs -----------------
__global__ __launch_bounds__(128) void k_contract(
    const int* __restrict__ ei, const float* __restrict__ B3,
    const float* __restrict__ CW1, const float* __restrict__ CB1,
    const float* __restrict__ CW2) {
    __shared__ float  s_cw1[32][32];
    __shared__ float4 s_k2[4][2][32];
    int t = threadIdx.x, lane = t & 31, w = t >> 5;
    for (int i = t; i < 1024; i += 128) ((float*)s_cw1)[i] = CW1[i];
    __syncthreads();

    int n = blockIdx.x * 4 + w;
    if (n >= NN) return;
    int beg = g_cptr[n], end = g_cptr[n + 1];
    if (beg == end) return;

    float r[128];
    const float* wp = g_W3h + (size_t)n * 4096 + lane;
#pragma unroll
    for (int c = 0; c < 128; c++) r[c] = wp[c * 32];

    float hv = g_h[n * 32 + lane];
    float bh = 0.f;
#pragma unroll
    for (int j = 0; j < 32; j++)
        bh = fmaf(B3[lane * 32 + j], __shfl_sync(0xffffffffu, hv, j), bh);

    float cc = (lane < 3) ? g_coord[n * 3 + lane] : 0.f;
    float cb1l = CB1[lane], cw2l = CW2[lane];

    int e = g_ebc[beg];
    float4 kq = *(const float4*)(g_k2 + (size_t)e * 128 + lane * 4);
    for (int p = beg; p < end; p++) {
        int buf = p & 1;
        s_k2[w][buf][lane] = kq;
        int ecur = e;
        __syncwarp();
        if (p + 1 < end) {
            e = g_ebc[p + 1];
            kq = *(const float4*)(g_k2 + (size_t)e * 128 + lane * 4);
        }
        int rn = ei[ecur];
        float ma0 = bh, ma1 = 0.f, ma2 = 0.f, ma3 = 0.f;
        float mb0 = 0.f, mb1 = 0.f, mb2 = 0.f, mb3 = 0.f;
#pragma unroll
        for (int c = 0; c < 16; c++) {
            float4 kv = s_k2[w][buf][c];
            float4 kw = s_k2[w][buf][c + 16];
            ma0 = fmaf(kv.x, r[4 * c + 0], ma0);
            ma1 = fmaf(kv.y, r[4 * c + 1], ma1);
            ma2 = fmaf(kv.z, r[4 * c + 2], ma2);
            ma3 = fmaf(kv.w, r[4 * c + 3], ma3);
            mb0 = fmaf(kw.x, r[64 + 4 * c + 0], mb0);
            mb1 = fmaf(kw.y, r[64 + 4 * c + 1], mb1);
            mb2 = fmaf(kw.z, r[64 + 4 * c + 2], mb2);
            mb3 = fmaf(kw.w, r[64 + 4 * c + 3], mb3);
        }
        float m = ((ma0 + ma1) + (ma2 + ma3)) + ((mb0 + mb1) + (mb2 + mb3));

        float t0 = cb1l, t1 = 0.f, t2 = 0.f, t3 = 0.f;
#pragma unroll
        for (int i = 0; i < 8; i++) {
            t0 = fmaf(__shfl_sync(0xffffffffu, m, 4 * i + 0), s_cw1[4 * i + 0][lane], t0);
            t1 = fmaf(__shfl_sync(0xffffffffu, m, 4 * i + 1), s_cw1[4 * i + 1][lane], t1);
            t2 = fmaf(__shfl_sync(0xffffffffu, m, 4 * i + 2), s_cw1[4 * i + 2][lane], t2);
            t3 = fmaf(__shfl_sync(0xffffffffu, m, 4 * i + 3), s_cw1[4 * i + 3][lane], t3);
        }
        float tj = fmaxf((t0 + t1) + (t2 + t3), 0.f) * cw2l;
#pragma unroll
        for (int o = 16; o; o >>= 1) tj += __shfl_xor_sync(0xffffffffu, tj, o);

        atomicAdd(&g_acch[rn * 32 + lane], m);
        if (lane < 3)
            atomicAdd(&g_accc[rn * 3 + lane], (g_coord[rn * 3 + lane] - cc) * tj);
    }
}

// ---------------- node update (invc inlined) --------------------------------------
__global__ void k_update() {
    int idx = blockIdx.x * blockDim.x + threadIdx.x;
    if (idx >= NN * 32) return;
    int n = idx >> 5, j = idx & 31;
    int c = g_cntr[n];
    float inv = 1.f / (float)(c > 0 ? c : 1);
    g_h[idx] = fmaxf(g_h[idx] + g_acch[idx] * inv, 0.f);
    g_acch[idx] = 0.f;
    if (j < 3) {
        g_coord[n * 3 + j] += g_accc[n * 3 + j] * inv;
        g_accc[n * 3 + j] = 0.f;
    }
}

// ---------------- final MLP + coord copy ------------------------------------------
__global__ void k_final(const float* __restrict__ w1, const float* __restrict__ b1,
                        const float* __restrict__ w2, const float* __restrict__ b2,
                        float* __restrict__ out) {
    int gid = blockIdx.x * blockDim.x + threadIdx.x;
    if (gid < NN * 3) out[NN + gid] = g_coord[gid];
    int lane = gid & 31;
    int n = gid >> 5;
    if (n >= NN) return;
    float hv = g_h[n * 32 + lane];
    float t0 = b1[lane], t1 = b1[32 + lane];
#pragma unroll
    for (int j = 0; j < 32; j++) {
        float hj = __shfl_sync(0xffffffffu, hv, j);
        t0 = fmaf(hj, w1[j * 64 + lane], t0);
        t1 = fmaf(hj, w1[j * 64 + 32 + lane], t1);
    }
    float s = fmaxf(t0, 0.f) * w2[lane] + fmaxf(t1, 0.f) * w2[32 + lane];
#pragma unroll
    for (int o = 16; o; o >>= 1) s += __shfl_xor_sync(0xffffffffu, s, o);
    if (lane == 0) out[n] = s + b2[0];
}

// ---------------------------------------------------------------------------------
extern "C" void kernel_launch(void* const* d_in, const int* in_sizes, int n_in,
                              void* d_out, int out_size) {
    const float* x    = (const float*)d_in[0];
    const int*   ei   = (const int*)d_in[1];
    const float* attr = (const float*)d_in[2];
    const float* f1w  = (const float*)d_in[4];
    const float* f1b  = (const float*)d_in[5];
    const float* kw1  = (const float*)d_in[6];
    const float* kb1  = (const float*)d_in[7];
    const float* kw2  = (const float*)d_in[8];
    const float* kb2  = (const float*)d_in[9];
    const float* kw3  = (const float*)d_in[10];
    const float* kb3  = (const float*)d_in[11];
    const float* cw1  = (const float*)d_in[12];
    const float* cb1  = (const float*)d_in[13];
    const float* cw2  = (const float*)d_in[14];
    const float* f2w1 = (const float*)d_in[15];
    const float* f2b1 = (const float*)d_in[16];
    const float* f2w2 = (const float*)d_in[17];
    const float* f2b2 = (const float*)d_in[18];
    const float* ci   = (const float*)d_in[3];
    float* out = (float*)d_out;

    int fused_grid = EDGE_BLOCKS + W3H_BLOCKS;

    k_prep<<<(NN * 32 + 255) / 256, 256>>>(x, f1w, f1b, ci);     // 0
    k_csr<<<1, 1024>>>(ei);                                       // 1
    for (int L = 0; L < 3; L++) {
        k_edge_w3h<<<fused_grid, 256>>>(ei, attr, kw1, kb1, kw2, kb2, kw3);  // 2 (L0)
        k_contract<<<(NN + 3) / 4, 128>>>(ei, kb3, cw1, cb1, cw2);           // 3 (L0) <- profiled
        k_update<<<(NN * 32 + 255) / 256, 256>>>();                          // 4 (L0)
    }
    k_final<<<(NN * 32 + 255) / 256, 256>>>(f2w1, f2b1, f2w2, f2b2, out);
}

// round 5
// speedup vs baseline: 1.1074x; 1.1074x over previous
#include <cuda_runtime.h>
#include <cuda_fp16.h>

#define NN 10000
#define EE 100000

// ---------------- scratch (static device globals; no allocation) ----------------
__device__ float g_h[NN * 32];
__device__ float g_coord[NN * 3];
__device__ float g_k2[(size_t)EE * 128];
__device__ __align__(16) __half g_W3hH[(size_t)NN * 4096];  // [n][cg:16][i:32][cw:8]
__device__ float g_acch[NN * 32];
__device__ float g_accc[NN * 3];
__device__ int   g_cntc[NN];
__device__ int   g_cntr[NN];
__device__ int   g_fill[NN];
__device__ int   g_cptr[NN + 1];
__device__ int   g_ebc[EE];

__device__ __forceinline__ unsigned f2tf32(float f) {
    unsigned u;
    asm("cvt.rna.tf32.f32 %0, %1;" : "=r"(u) : "f"(f));
    return u;
}
__device__ __forceinline__ void split_tf32(float x, unsigned& hi, unsigned& lo) {
    hi = f2tf32(x);
    lo = f2tf32(x - __uint_as_float(hi));
}
__device__ __forceinline__ void mma_tf32(float& c0, float& c1, float& c2, float& c3,
                                         unsigned a0, unsigned a1, unsigned a2, unsigned a3,
                                         unsigned b0, unsigned b1) {
    asm("mma.sync.aligned.m16n8k8.row.col.f32.tf32.tf32.f32 "
        "{%0,%1,%2,%3}, {%4,%5,%6,%7}, {%8,%9}, {%0,%1,%2,%3};"
        : "+f"(c0), "+f"(c1), "+f"(c2), "+f"(c3)
        : "r"(a0), "r"(a1), "r"(a2), "r"(a3), "r"(b0), "r"(b1));
}
__device__ __forceinline__ float2 h2f2(unsigned u) {
    __half2 h = *reinterpret_cast<__half2*>(&u);
    return __half22float2(h);
}

// ---------------- init ----------------
__global__ void k_prep(const float* __restrict__ x, const float* __restrict__ w,
                       const float* __restrict__ b, const float* __restrict__ ci) {
    int idx = blockIdx.x * blockDim.x + threadIdx.x;
    if (idx < NN * 32) {
        int n = idx >> 5, j = idx & 31;
        float s = b[j];
        s += x[n * 3 + 0] * w[j] + x[n * 3 + 1] * w[32 + j] + x[n * 3 + 2] * w[64 + j];
        g_h[idx] = s;
        g_acch[idx] = 0.f;
    }
    if (idx < NN * 3) { g_coord[idx] = ci[idx]; g_accc[idx] = 0.f; }
    if (idx < NN) { g_cntc[idx] = 0; g_cntr[idx] = 0; g_fill[idx] = 0; }
}

__global__ void k_hist(const int* __restrict__ ei) {
    int e = blockIdx.x * blockDim.x + threadIdx.x;
    if (e < EE) {
        atomicAdd(&g_cntr[ei[e]], 1);
        atomicAdd(&g_cntc[ei[EE + e]], 1);
    }
}

__global__ void k_scan() {
    __shared__ int ss[1024];
    int t = threadIdx.x;
    int base = t * 10;
    int loc[10];
    int s = 0;
#pragma unroll
    for (int i = 0; i < 10; i++) {
        int v = (base + i < NN) ? g_cntc[base + i] : 0;
        loc[i] = s; s += v;
    }
    ss[t] = s;
    __syncthreads();
    for (int off = 1; off < 1024; off <<= 1) {
        int v = (t >= off) ? ss[t - off] : 0;
        __syncthreads();
        ss[t] += v;
        __syncthreads();
    }
    int pre = (t > 0) ? ss[t - 1] : 0;
#pragma unroll
    for (int i = 0; i < 10; i++)
        if (base + i < NN) g_cptr[base + i] = pre + loc[i];
    if (t == 1023) g_cptr[NN] = ss[1023];
}

__global__ void k_scatter(const int* __restrict__ ei) {
    int e = blockIdx.x * blockDim.x + threadIdx.x;
    if (e < EE) {
        int c = ei[EE + e];
        int p = g_cptr[c] + atomicAdd(&g_fill[c], 1);
        g_ebc[p] = e;
    }
}

// -------- edge MLP (R3 scalar version, proven 59us) -------------------------------
__global__ __launch_bounds__(256) void k_edge_mlp(
    const int* __restrict__ ei, const float* __restrict__ attr,
    const float* __restrict__ W1, const float* __restrict__ B1,
    const float* __restrict__ W2, const float* __restrict__ B2) {
    __shared__ float s_kin[32][9];
    __shared__ float s_k1[64][36];
    __shared__ float s_w2[64][132];
    __shared__ float s_w1[7 * 64];
    __shared__ float s_b1[64];
    __shared__ float s_b2[128];
    int t = threadIdx.x;
    int e0 = blockIdx.x * 32;

    for (int i = t; i < 7 * 64; i += 256) s_w1[i] = W1[i];
    if (t < 64) s_b1[t] = B1[t];
    else if (t < 192) s_b2[t - 64] = B2[t - 64];
    for (int i = t; i < 64 * 32; i += 256) {
        int k = i >> 5, q = i & 31;
        *(float4*)&s_w2[k][q * 4] = *(const float4*)&W2[k * 128 + q * 4];
    }

    if (t < 32) {
        int e = e0 + t;
        float rad = 0.f;
        if (e < EE) {
            int r = ei[e], c = ei[EE + e];
            float d0 = g_coord[r * 3 + 0] - g_coord[c * 3 + 0];
            float d1 = g_coord[r * 3 + 1] - g_coord[c * 3 + 1];
            float d2 = g_coord[r * 3 + 2] - g_coord[c * 3 + 2];
            rad = d0 * d0 + d1 * d1 + d2 * d2;
#pragma unroll
            for (int q = 0; q < 6; q++) s_kin[t][q] = attr[e * 6 + q];
        } else {
#pragma unroll
            for (int q = 0; q < 6; q++) s_kin[t][q] = 0.f;
        }
        s_kin[t][6] = rad;
        s_kin[t][7] = 0.f;
        s_kin[t][8] = 0.f;
    }
    __syncthreads();

    for (int i = t; i < 64 * 32; i += 256) {
        int c = i >> 5, e = i & 31;
        float s = s_b1[c];
#pragma unroll
        for (int q = 0; q < 7; q++) s = fmaf(s_kin[e][q], s_w1[q * 64 + c], s);
        s_k1[c][e] = fmaxf(s, 0.f);
    }
    __syncthreads();

    int tx = t & 31, ey = t >> 5;
    float acc[4][4];
#pragma unroll
    for (int i = 0; i < 4; i++)
#pragma unroll
        for (int j = 0; j < 4; j++) acc[i][j] = 0.f;

#pragma unroll
    for (int k = 0; k < 64; k++) {
        float4 av = *(const float4*)&s_k1[k][ey * 4];
        float4 bv = *(const float4*)&s_w2[k][tx * 4];
        float a[4] = {av.x, av.y, av.z, av.w};
        float b[4] = {bv.x, bv.y, bv.z, bv.w};
#pragma unroll
        for (int i = 0; i < 4; i++)
#pragma unroll
            for (int j = 0; j < 4; j++) acc[i][j] = fmaf(a[i], b[j], acc[i][j]);
    }
    float4 b2v = *(const float4*)&s_b2[tx * 4];
#pragma unroll
    for (int i = 0; i < 4; i++) {
        int e = e0 + ey * 4 + i;
        if (e < EE) {
            float4 r;
            r.x = fmaxf(acc[i][0] + b2v.x, 0.f);
            r.y = fmaxf(acc[i][1] + b2v.y, 0.f);
            r.z = fmaxf(acc[i][2] + b2v.z, 0.f);
            r.w = fmaxf(acc[i][3] + b2v.w, 0.f);
            *(float4*)&g_k2[(size_t)e * 128 + tx * 4] = r;
        }
    }
}

// -------- W3h via tf32 mma (3-mma split) -> fp16 chunk-transposed output ----------
// Block: 64 nodes x 256 outs (one cg = 8 consecutive c). Epilogue: smem transpose.
struct SmemW3h {
    float a[64][36];
    float b[256][36];
};
__global__ __launch_bounds__(256) void k_w3h_mma(const float* __restrict__ W3) {
    constexpr unsigned SB = sizeof(SmemW3h) > 32768u ? sizeof(SmemW3h) : 32768u;
    __shared__ __align__(16) char sb[SB];
    SmemW3h& sm = *(SmemW3h*)sb;
    int t = threadIdx.x, warp = t >> 5, lane = t & 31;
    int cg = blockIdx.x & 15;
    int o0 = cg * 256, n0 = (blockIdx.x >> 4) * 64;

    for (int i = t; i < 64 * 8; i += 256) {
        int n = i >> 3, kq = i & 7;
        float4 v = make_float4(0.f, 0.f, 0.f, 0.f);
        if (n0 + n < NN) v = *(const float4*)&g_h[(n0 + n) * 32 + kq * 4];
        sm.a[n][kq * 4 + 0] = v.x; sm.a[n][kq * 4 + 1] = v.y;
        sm.a[n][kq * 4 + 2] = v.z; sm.a[n][kq * 4 + 3] = v.w;
    }
    for (int i = t; i < 256 * 8; i += 256) {
        int o = i >> 3, kq = i & 7;
        float4 v = *(const float4*)&W3[(size_t)(o0 + o) * 32 + kq * 4];
        sm.b[o][kq * 4 + 0] = v.x; sm.b[o][kq * 4 + 1] = v.y;
        sm.b[o][kq * 4 + 2] = v.z; sm.b[o][kq * 4 + 3] = v.w;
    }
    __syncthreads();

    int wm = warp & 3, wn = warp >> 2;
    int qr = lane >> 2, qc = lane & 3;
    float acc[16][4];
#pragma unroll
    for (int nt = 0; nt < 16; nt++)
#pragma unroll
        for (int j = 0; j < 4; j++) acc[nt][j] = 0.f;

#pragma unroll
    for (int ks = 0; ks < 4; ks++) {
        int k0 = ks * 8;
        unsigned ah[4], al[4];
        split_tf32(sm.a[wm * 16 + qr][k0 + qc],     ah[0], al[0]);
        split_tf32(sm.a[wm * 16 + qr + 8][k0 + qc], ah[1], al[1]);
        split_tf32(sm.a[wm * 16 + qr][k0 + qc + 4],     ah[2], al[2]);
        split_tf32(sm.a[wm * 16 + qr + 8][k0 + qc + 4], ah[3], al[3]);
#pragma unroll
        for (int nt = 0; nt < 16; nt++) {
            int ob = wn * 128 + nt * 8;
            unsigned bh0, bl0, bh1, bl1;
            split_tf32(sm.b[ob + qr][k0 + qc],     bh0, bl0);
            split_tf32(sm.b[ob + qr][k0 + qc + 4], bh1, bl1);
            mma_tf32(acc[nt][0], acc[nt][1], acc[nt][2], acc[nt][3],
                     ah[0], ah[1], ah[2], ah[3], bh0, bh1);
            mma_tf32(acc[nt][0], acc[nt][1], acc[nt][2], acc[nt][3],
                     al[0], al[1], al[2], al[3], bh0, bh1);
            mma_tf32(acc[nt][0], acc[nt][1], acc[nt][2], acc[nt][3],
                     ah[0], ah[1], ah[2], ah[3], bl0, bl1);
        }
    }
    __syncthreads();   // A/B staging no longer needed; reuse as fp16 out tile

    // stage fp16 transpose: so[n_local*256 + i*8 + cw], o_local = cw*32 + i
    __half* so = (__half*)sb;
    int nlA = wm * 16 + qr, nlB = nlA + 8;
#pragma unroll
    for (int nt = 0; nt < 16; nt++) {
#pragma unroll
        for (int j = 0; j < 2; j++) {
            int ol = wn * 128 + nt * 8 + 2 * qc + j;
            int cw = ol >> 5, i = ol & 31;
            so[nlA * 256 + i * 8 + cw] = __float2half(acc[nt][j]);
            so[nlB * 256 + i * 8 + cw] = __float2half(acc[nt][2 + j]);
        }
    }
    __syncthreads();

    // coalesced copy out: 2048 int4 (64 n x 32 int4)
    uint4* dst = (uint4*)g_W3hH;
    const uint4* src = (const uint4*)so;
    for (int i = t; i < 2048; i += 256) {
        int nl = i >> 5, sub = i & 31;
        int n = n0 + nl;
        if (n < NN) dst[(size_t)n * 512 + cg * 32 + sub] = src[i];
    }
}

// -------- contraction: warp per col-node; W3h row as 16 x uint4 (fp16) ------------
__global__ __launch_bounds__(128) void k_contract(
    const int* __restrict__ ei, const float* __restrict__ B3,
    const float* __restrict__ CW1, const float* __restrict__ CB1,
    const float* __restrict__ CW2) {
    __shared__ float  s_cw1[32][32];
    __shared__ float4 s_k2[4][2][32];
    int t = threadIdx.x, lane = t & 31, w = t >> 5;
    for (int i = t; i < 1024; i += 128) ((float*)s_cw1)[i] = CW1[i];
    __syncthreads();

    int n = blockIdx.x * 4 + w;
    if (n >= NN) return;
    int beg = g_cptr[n], end = g_cptr[n + 1];
    if (beg == end) return;

    uint4 rq[16];
    const uint4* wp = (const uint4*)g_W3hH + (size_t)n * 512 + lane;
#pragma unroll
    for (int cg = 0; cg < 16; cg++) rq[cg] = wp[cg * 32];

    float hv = g_h[n * 32 + lane];
    float bh = 0.f;
#pragma unroll
    for (int j = 0; j < 32; j++)
        bh = fmaf(B3[lane * 32 + j], __shfl_sync(0xffffffffu, hv, j), bh);

    float cc = (lane < 3) ? g_coord[n * 3 + lane] : 0.f;
    float cb1l = CB1[lane], cw2l = CW2[lane];

    int e = g_ebc[beg];
    float4 kq = *(const float4*)(g_k2 + (size_t)e * 128 + lane * 4);
    for (int p = beg; p < end; p++) {
        int buf = p & 1;
        s_k2[w][buf][lane] = kq;
        int ecur = e;
        __syncwarp();
        if (p + 1 < end) {
            e = g_ebc[p + 1];
            kq = *(const float4*)(g_k2 + (size_t)e * 128 + lane * 4);
        }
        int rn = ei[ecur];
        float m0 = bh, m1 = 0.f, m2 = 0.f, m3 = 0.f;
#pragma unroll
        for (int cg = 0; cg < 16; cg++) {
            float4 ka = s_k2[w][buf][2 * cg];
            float4 kb = s_k2[w][buf][2 * cg + 1];
            uint4  q  = rq[cg];
            float2 w0 = h2f2(q.x), w1 = h2f2(q.y), w2 = h2f2(q.z), w3 = h2f2(q.w);
            m0 = fmaf(ka.x, w0.x, m0); m1 = fmaf(ka.y, w0.y, m1);
            m2 = fmaf(ka.z, w1.x, m2); m3 = fmaf(ka.w, w1.y, m3);
            m0 = fmaf(kb.x, w2.x, m0); m1 = fmaf(kb.y, w2.y, m1);
            m2 = fmaf(kb.z, w3.x, m2); m3 = fmaf(kb.w, w3.y, m3);
        }
        float m = (m0 + m1) + (m2 + m3);

        float t0 = cb1l, t1 = 0.f, t2 = 0.f, t3 = 0.f;
#pragma unroll
        for (int i = 0; i < 8; i++) {
            t0 = fmaf(__shfl_sync(0xffffffffu, m, 4 * i + 0), s_cw1[4 * i + 0][lane], t0);
            t1 = fmaf(__shfl_sync(0xffffffffu, m, 4 * i + 1), s_cw1[4 * i + 1][lane], t1);
            t2 = fmaf(__shfl_sync(0xffffffffu, m, 4 * i + 2), s_cw1[4 * i + 2][lane], t2);
            t3 = fmaf(__shfl_sync(0xffffffffu, m, 4 * i + 3), s_cw1[4 * i + 3][lane], t3);
        }
        float tj = fmaxf((t0 + t1) + (t2 + t3), 0.f) * cw2l;
#pragma unroll
        for (int o = 16; o; o >>= 1) tj += __shfl_xor_sync(0xffffffffu, tj, o);

        atomicAdd(&g_acch[rn * 32 + lane], m);
        if (lane < 3)
            atomicAdd(&g_accc[rn * 3 + lane], (g_coord[rn * 3 + lane] - cc) * tj);
    }
}

// ---------------- node update (invc inlined) --------------------------------------
__global__ void k_update() {
    int idx = blockIdx.x * blockDim.x + threadIdx.x;
    if (idx >= NN * 32) return;
    int n = idx >> 5, j = idx & 31;
    int c = g_cntr[n];
    float inv = 1.f / (float)(c > 0 ? c : 1);
    g_h[idx] = fmaxf(g_h[idx] + g_acch[idx] * inv, 0.f);
    g_acch[idx] = 0.f;
    if (j < 3) {
        g_coord[n * 3 + j] += g_accc[n * 3 + j] * inv;
        g_accc[n * 3 + j] = 0.f;
    }
}

// ---------------- final MLP + coord copy ------------------------------------------
__global__ void k_final(const float* __restrict__ w1, const float* __restrict__ b1,
                        const float* __restrict__ w2, const float* __restrict__ b2,
                        float* __restrict__ out) {
    int gid = blockIdx.x * blockDim.x + threadIdx.x;
    if (gid < NN * 3) out[NN + gid] = g_coord[gid];
    int lane = gid & 31;
    int n = gid >> 5;
    if (n >= NN) return;
    float hv = g_h[n * 32 + lane];
    float t0 = b1[lane], t1 = b1[32 + lane];
#pragma unroll
    for (int j = 0; j < 32; j++) {
        float hj = __shfl_sync(0xffffffffu, hv, j);
        t0 = fmaf(hj, w1[j * 64 + lane], t0);
        t1 = fmaf(hj, w1[j * 64 + 32 + lane], t1);
    }
    float s = fmaxf(t0, 0.f) * w2[lane] + fmaxf(t1, 0.f) * w2[32 + lane];
#pragma unroll
    for (int o = 16; o; o >>= 1) s += __shfl_xor_sync(0xffffffffu, s, o);
    if (lane == 0) out[n] = s + b2[0];
}

// ---------------------------------------------------------------------------------
extern "C" void kernel_launch(void* const* d_in, const int* in_sizes, int n_in,
                              void* d_out, int out_size) {
    const float* x    = (const float*)d_in[0];
    const int*   ei   = (const int*)d_in[1];
    const float* attr = (const float*)d_in[2];
    const float* ci   = (const float*)d_in[3];
    const float* f1w  = (const float*)d_in[4];
    const float* f1b  = (const float*)d_in[5];
    const float* kw1  = (const float*)d_in[6];
    const float* kb1  = (const float*)d_in[7];
    const float* kw2  = (const float*)d_in[8];
    const float* kb2  = (const float*)d_in[9];
    const float* kw3  = (const float*)d_in[10];
    const float* kb3  = (const float*)d_in[11];
    const float* cw1  = (const float*)d_in[12];
    const float* cb1  = (const float*)d_in[13];
    const float* cw2  = (const float*)d_in[14];
    const float* f2w1 = (const float*)d_in[15];
    const float* f2b1 = (const float*)d_in[16];
    const float* f2w2 = (const float*)d_in[17];
    const float* f2b2 = (const float*)d_in[18];
    float* out = (float*)d_out;

    int w3h_grid = ((NN + 63) / 64) * 16;

    k_prep<<<(NN * 32 + 255) / 256, 256>>>(x, f1w, f1b, ci);   // 0
    k_hist<<<(EE + 255) / 256, 256>>>(ei);                      // 1
    k_scan<<<1, 1024>>>();                                      // 2
    k_w3h_mma<<<w3h_grid, 256>>>(kw3);                          // 3 <- profiled (L0 w3h)
    k_scatter<<<(EE + 255) / 256, 256>>>(ei);                   // 4
    k_edge_mlp<<<(EE + 31) / 32, 256>>>(ei, attr, kw1, kb1, kw2, kb2);  // 5 (L0)
    k_contract<<<(NN + 3) / 4, 128>>>(ei, kb3, cw1, cb1, cw2);          // 6 (L0)
    k_update<<<(NN * 32 + 255) / 256, 256>>>();                         // 7 (L0)

    for (int L = 1; L < 3; L++) {
        k_edge_mlp<<<(EE + 31) / 32, 256>>>(ei, attr, kw1, kb1, kw2, kb2);
        k_w3h_mma<<<w3h_grid, 256>>>(kw3);
        k_contract<<<(NN + 3) / 4, 128>>>(ei, kb3, cw1, cb1, cw2);
        k_update<<<(NN * 32 + 255) / 256, 256>>>();
    }

    k_final<<<(NN * 32 + 255) / 256, 256>>>(f2w1, f2b1, f2w2, f2b2, out);
}

// round 6
// speedup vs baseline: 1.1888x; 1.0734x over previous
#include <cuda_runtime.h>
#include <cuda_fp16.h>

#define NN 10000
#define EE 100000

// ---------------- scratch (static device globals; no allocation) ----------------
__device__ float g_h[NN * 32];
__device__ float g_coord[NN * 3];
__device__ float g_k2[(size_t)EE * 128];
__device__ __align__(16) __half g_W3hH[(size_t)NN * 4096];  // [n][cg:16][i:32][cw:8]
__device__ float g_acch[NN * 32];
__device__ float g_accc[NN * 3];
__device__ int   g_cntc[NN];
__device__ int   g_cntr[NN];
__device__ int   g_fill[NN];
__device__ int   g_cptr[NN + 1];
__device__ int   g_ebc[EE];

__device__ __forceinline__ unsigned f2tf32(float f) {
    unsigned u;
    asm("cvt.rna.tf32.f32 %0, %1;" : "=r"(u) : "f"(f));
    return u;
}
__device__ __forceinline__ void mma_tf32(float& c0, float& c1, float& c2, float& c3,
                                         unsigned a0, unsigned a1, unsigned a2, unsigned a3,
                                         unsigned b0, unsigned b1) {
    asm("mma.sync.aligned.m16n8k8.row.col.f32.tf32.tf32.f32 "
        "{%0,%1,%2,%3}, {%4,%5,%6,%7}, {%8,%9}, {%0,%1,%2,%3};"
        : "+f"(c0), "+f"(c1), "+f"(c2), "+f"(c3)
        : "r"(a0), "r"(a1), "r"(a2), "r"(a3), "r"(b0), "r"(b1));
}
__device__ __forceinline__ float2 h2f2(unsigned u) {
    __half2 h = *reinterpret_cast<__half2*>(&u);
    return __half22float2(h);
}

// ---------------- init ----------------
__global__ void k_prep(const float* __restrict__ x, const float* __restrict__ w,
                       const float* __restrict__ b, const float* __restrict__ ci) {
    int idx = blockIdx.x * blockDim.x + threadIdx.x;
    if (idx < NN * 32) {
        int n = idx >> 5, j = idx & 31;
        float s = b[j];
        s += x[n * 3 + 0] * w[j] + x[n * 3 + 1] * w[32 + j] + x[n * 3 + 2] * w[64 + j];
        g_h[idx] = s;
        g_acch[idx] = 0.f;
    }
    if (idx < NN * 3) { g_coord[idx] = ci[idx]; g_accc[idx] = 0.f; }
    if (idx < NN) { g_cntc[idx] = 0; g_cntr[idx] = 0; g_fill[idx] = 0; }
}

__global__ void k_hist(const int* __restrict__ ei) {
    int e = blockIdx.x * blockDim.x + threadIdx.x;
    if (e < EE) {
        atomicAdd(&g_cntr[ei[e]], 1);
        atomicAdd(&g_cntc[ei[EE + e]], 1);
    }
}

__global__ void k_scan() {
    __shared__ int ss[1024];
    int t = threadIdx.x;
    int base = t * 10;
    int loc[10];
    int s = 0;
#pragma unroll
    for (int i = 0; i < 10; i++) {
        int v = (base + i < NN) ? g_cntc[base + i] : 0;
        loc[i] = s; s += v;
    }
    ss[t] = s;
    __syncthreads();
    for (int off = 1; off < 1024; off <<= 1) {
        int v = (t >= off) ? ss[t - off] : 0;
        __syncthreads();
        ss[t] += v;
        __syncthreads();
    }
    int pre = (t > 0) ? ss[t - 1] : 0;
#pragma unroll
    for (int i = 0; i < 10; i++)
        if (base + i < NN) g_cptr[base + i] = pre + loc[i];
    if (t == 1023) g_cptr[NN] = ss[1023];
}

__global__ void k_scatter(const int* __restrict__ ei) {
    int e = blockIdx.x * blockDim.x + threadIdx.x;
    if (e < EE) {
        int c = ei[EE + e];
        int p = g_cptr[c] + atomicAdd(&g_fill[c], 1);
        g_ebc[p] = e;
    }
}

// -------- edge MLP (scalar, proven) -----------------------------------------------
__global__ __launch_bounds__(256) void k_edge_mlp(
    const int* __restrict__ ei, const float* __restrict__ attr,
    const float* __restrict__ W1, const float* __restrict__ B1,
    const float* __restrict__ W2, const float* __restrict__ B2) {
    __shared__ float s_kin[32][9];
    __shared__ float s_k1[64][36];
    __shared__ float s_w2[64][132];
    __shared__ float s_w1[7 * 64];
    __shared__ float s_b1[64];
    __shared__ float s_b2[128];
    int t = threadIdx.x;
    int e0 = blockIdx.x * 32;

    for (int i = t; i < 7 * 64; i += 256) s_w1[i] = W1[i];
    if (t < 64) s_b1[t] = B1[t];
    else if (t < 192) s_b2[t - 64] = B2[t - 64];
    for (int i = t; i < 64 * 32; i += 256) {
        int k = i >> 5, q = i & 31;
        *(float4*)&s_w2[k][q * 4] = *(const float4*)&W2[k * 128 + q * 4];
    }

    if (t < 32) {
        int e = e0 + t;
        float rad = 0.f;
        if (e < EE) {
            int r = ei[e], c = ei[EE + e];
            float d0 = g_coord[r * 3 + 0] - g_coord[c * 3 + 0];
            float d1 = g_coord[r * 3 + 1] - g_coord[c * 3 + 1];
            float d2 = g_coord[r * 3 + 2] - g_coord[c * 3 + 2];
            rad = d0 * d0 + d1 * d1 + d2 * d2;
#pragma unroll
            for (int q = 0; q < 6; q++) s_kin[t][q] = attr[e * 6 + q];
        } else {
#pragma unroll
            for (int q = 0; q < 6; q++) s_kin[t][q] = 0.f;
        }
        s_kin[t][6] = rad;
        s_kin[t][7] = 0.f;
        s_kin[t][8] = 0.f;
    }
    __syncthreads();

    for (int i = t; i < 64 * 32; i += 256) {
        int c = i >> 5, e = i & 31;
        float s = s_b1[c];
#pragma unroll
        for (int q = 0; q < 7; q++) s = fmaf(s_kin[e][q], s_w1[q * 64 + c], s);
        s_k1[c][e] = fmaxf(s, 0.f);
    }
    __syncthreads();

    int tx = t & 31, ey = t >> 5;
    float acc[4][4];
#pragma unroll
    for (int i = 0; i < 4; i++)
#pragma unroll
        for (int j = 0; j < 4; j++) acc[i][j] = 0.f;

#pragma unroll
    for (int k = 0; k < 64; k++) {
        float4 av = *(const float4*)&s_k1[k][ey * 4];
        float4 bv = *(const float4*)&s_w2[k][tx * 4];
        float a[4] = {av.x, av.y, av.z, av.w};
        float b[4] = {bv.x, bv.y, bv.z, bv.w};
#pragma unroll
        for (int i = 0; i < 4; i++)
#pragma unroll
            for (int j = 0; j < 4; j++) acc[i][j] = fmaf(a[i], b[j], acc[i][j]);
    }
    float4 b2v = *(const float4*)&s_b2[tx * 4];
#pragma unroll
    for (int i = 0; i < 4; i++) {
        int e = e0 + ey * 4 + i;
        if (e < EE) {
            float4 r;
            r.x = fmaxf(acc[i][0] + b2v.x, 0.f);
            r.y = fmaxf(acc[i][1] + b2v.y, 0.f);
            r.z = fmaxf(acc[i][2] + b2v.z, 0.f);
            r.w = fmaxf(acc[i][3] + b2v.w, 0.f);
            *(float4*)&g_k2[(size_t)e * 128 + tx * 4] = r;
        }
    }
}

// -------- W3h via single tf32 mma (cvt at staging) -> fp16 chunk-transposed -------
struct SmemW3h {
    unsigned a[64][36];
    unsigned b[256][36];
};
__global__ __launch_bounds__(256) void k_w3h_mma(const float* __restrict__ W3) {
    constexpr unsigned SB = sizeof(SmemW3h) > 32768u ? sizeof(SmemW3h) : 32768u;
    __shared__ __align__(16) char sb[SB];
    SmemW3h& sm = *(SmemW3h*)sb;
    int t = threadIdx.x, warp = t >> 5, lane = t & 31;
    int cg = blockIdx.x & 15;
    int o0 = cg * 256, n0 = (blockIdx.x >> 4) * 64;

    // stage A (tf32-converted once)
    for (int i = t; i < 64 * 8; i += 256) {
        int n = i >> 3, kq = i & 7;
        float4 v = make_float4(0.f, 0.f, 0.f, 0.f);
        if (n0 + n < NN) v = *(const float4*)&g_h[(n0 + n) * 32 + kq * 4];
        sm.a[n][kq * 4 + 0] = f2tf32(v.x); sm.a[n][kq * 4 + 1] = f2tf32(v.y);
        sm.a[n][kq * 4 + 2] = f2tf32(v.z); sm.a[n][kq * 4 + 3] = f2tf32(v.w);
    }
    // stage B (tf32-converted once)
    for (int i = t; i < 256 * 8; i += 256) {
        int o = i >> 3, kq = i & 7;
        float4 v = *(const float4*)&W3[(size_t)(o0 + o) * 32 + kq * 4];
        sm.b[o][kq * 4 + 0] = f2tf32(v.x); sm.b[o][kq * 4 + 1] = f2tf32(v.y);
        sm.b[o][kq * 4 + 2] = f2tf32(v.z); sm.b[o][kq * 4 + 3] = f2tf32(v.w);
    }
    __syncthreads();

    int wm = warp & 3, wn = warp >> 2;
    int qr = lane >> 2, qc = lane & 3;
    float acc[16][4];
#pragma unroll
    for (int nt = 0; nt < 16; nt++)
#pragma unroll
        for (int j = 0; j < 4; j++) acc[nt][j] = 0.f;

#pragma unroll
    for (int ks = 0; ks < 4; ks++) {
        int k0 = ks * 8;
        unsigned a0 = sm.a[wm * 16 + qr][k0 + qc];
        unsigned a1 = sm.a[wm * 16 + qr + 8][k0 + qc];
        unsigned a2 = sm.a[wm * 16 + qr][k0 + qc + 4];
        unsigned a3 = sm.a[wm * 16 + qr + 8][k0 + qc + 4];
#pragma unroll
        for (int nt = 0; nt < 16; nt++) {
            int ob = wn * 128 + nt * 8;
            unsigned b0 = sm.b[ob + qr][k0 + qc];
            unsigned b1 = sm.b[ob + qr][k0 + qc + 4];
            mma_tf32(acc[nt][0], acc[nt][1], acc[nt][2], acc[nt][3],
                     a0, a1, a2, a3, b0, b1);
        }
    }
    __syncthreads();   // staging dead; reuse as fp16 out tile

    // fp16 transpose: so[n_local*256 + i*8 + cw], o_local = cw*32 + i
    __half* so = (__half*)sb;
    int nlA = wm * 16 + qr, nlB = nlA + 8;
#pragma unroll
    for (int nt = 0; nt < 16; nt++) {
#pragma unroll
        for (int j = 0; j < 2; j++) {
            int ol = wn * 128 + nt * 8 + 2 * qc + j;
            int cw = ol >> 5, i = ol & 31;
            so[nlA * 256 + i * 8 + cw] = __float2half(acc[nt][j]);
            so[nlB * 256 + i * 8 + cw] = __float2half(acc[nt][2 + j]);
        }
    }
    __syncthreads();

    uint4* dst = (uint4*)g_W3hH;
    const uint4* src = (const uint4*)so;
    for (int i = t; i < 2048; i += 256) {
        int nl = i >> 5, sub = i & 31;
        int n = n0 + nl;
        if (n < NN) dst[(size_t)n * 512 + cg * 32 + sub] = src[i];
    }
}

// -------- contraction: warp per col-node; W3h row as 16 x uint4 (fp16) ------------
__global__ __launch_bounds__(128) void k_contract(
    const int* __restrict__ ei, const float* __restrict__ B3,
    const float* __restrict__ CW1, const float* __restrict__ CB1,
    const float* __restrict__ CW2) {
    __shared__ float  s_cw1[32][32];
    __shared__ float4 s_k2[4][2][32];
    int t = threadIdx.x, lane = t & 31, w = t >> 5;
    for (int i = t; i < 1024; i += 128) ((float*)s_cw1)[i] = CW1[i];
    __syncthreads();

    int n = blockIdx.x * 4 + w;
    if (n >= NN) return;
    int beg = g_cptr[n], end = g_cptr[n + 1];
    if (beg == end) return;

    uint4 rq[16];
    const uint4* wp = (const uint4*)g_W3hH + (size_t)n * 512 + lane;
#pragma unroll
    for (int cg = 0; cg < 16; cg++) rq[cg] = wp[cg * 32];

    float hv = g_h[n * 32 + lane];
    float bh = 0.f;
#pragma unroll
    for (int j = 0; j < 32; j++)
        bh = fmaf(B3[lane * 32 + j], __shfl_sync(0xffffffffu, hv, j), bh);

    float cc = (lane < 3) ? g_coord[n * 3 + lane] : 0.f;
    float cb1l = CB1[lane], cw2l = CW2[lane];

    int e = g_ebc[beg];
    float4 kq = *(const float4*)(g_k2 + (size_t)e * 128 + lane * 4);
    for (int p = beg; p < end; p++) {
        int buf = p & 1;
        s_k2[w][buf][lane] = kq;
        int ecur = e;
        __syncwarp();
        if (p + 1 < end) {
            e = g_ebc[p + 1];
            kq = *(const float4*)(g_k2 + (size_t)e * 128 + lane * 4);
        }
        int rn = ei[ecur];
        float m0 = bh, m1 = 0.f, m2 = 0.f, m3 = 0.f;
#pragma unroll
        for (int cg = 0; cg < 16; cg++) {
            float4 ka = s_k2[w][buf][2 * cg];
            float4 kb = s_k2[w][buf][2 * cg + 1];
            uint4  q  = rq[cg];
            float2 w0 = h2f2(q.x), w1 = h2f2(q.y), w2 = h2f2(q.z), w3 = h2f2(q.w);
            m0 = fmaf(ka.x, w0.x, m0); m1 = fmaf(ka.y, w0.y, m1);
            m2 = fmaf(ka.z, w1.x, m2); m3 = fmaf(ka.w, w1.y, m3);
            m0 = fmaf(kb.x, w2.x, m0); m1 = fmaf(kb.y, w2.y, m1);
            m2 = fmaf(kb.z, w3.x, m2); m3 = fmaf(kb.w, w3.y, m3);
        }
        float m = (m0 + m1) + (m2 + m3);

        float t0 = cb1l, t1 = 0.f, t2 = 0.f, t3 = 0.f;
#pragma unroll
        for (int i = 0; i < 8; i++) {
            t0 = fmaf(__shfl_sync(0xffffffffu, m, 4 * i + 0), s_cw1[4 * i + 0][lane], t0);
            t1 = fmaf(__shfl_sync(0xffffffffu, m, 4 * i + 1), s_cw1[4 * i + 1][lane], t1);
            t2 = fmaf(__shfl_sync(0xffffffffu, m, 4 * i + 2), s_cw1[4 * i + 2][lane], t2);
            t3 = fmaf(__shfl_sync(0xffffffffu, m, 4 * i + 3), s_cw1[4 * i + 3][lane], t3);
        }
        float tj = fmaxf((t0 + t1) + (t2 + t3), 0.f) * cw2l;
#pragma unroll
        for (int o = 16; o; o >>= 1) tj += __shfl_xor_sync(0xffffffffu, tj, o);

        atomicAdd(&g_acch[rn * 32 + lane], m);
        if (lane < 3)
            atomicAdd(&g_accc[rn * 3 + lane], (g_coord[rn * 3 + lane] - cc) * tj);
    }
}

// ---------------- node update (invc inlined) --------------------------------------
__global__ void k_update() {
    int idx = blockIdx.x * blockDim.x + threadIdx.x;
    if (idx >= NN * 32) return;
    int n = idx >> 5, j = idx & 31;
    int c = g_cntr[n];
    float inv = 1.f / (float)(c > 0 ? c : 1);
    g_h[idx] = fmaxf(g_h[idx] + g_acch[idx] * inv, 0.f);
    g_acch[idx] = 0.f;
    if (j < 3) {
        g_coord[n * 3 + j] += g_accc[n * 3 + j] * inv;
        g_accc[n * 3 + j] = 0.f;
    }
}

// ---------------- final MLP + coord copy ------------------------------------------
__global__ void k_final(const float* __restrict__ w1, const float* __restrict__ b1,
                        const float* __restrict__ w2, const float* __restrict__ b2,
                        float* __restrict__ out) {
    int gid = blockIdx.x * blockDim.x + threadIdx.x;
    if (gid < NN * 3) out[NN + gid] = g_coord[gid];
    int lane = gid & 31;
    int n = gid >> 5;
    if (n >= NN) return;
    float hv = g_h[n * 32 + lane];
    float t0 = b1[lane], t1 = b1[32 + lane];
#pragma unroll
    for (int j = 0; j < 32; j++) {
        float hj = __shfl_sync(0xffffffffu, hv, j);
        t0 = fmaf(hj, w1[j * 64 + lane], t0);
        t1 = fmaf(hj, w1[j * 64 + 32 + lane], t1);
    }
    float s = fmaxf(t0, 0.f) * w2[lane] + fmaxf(t1, 0.f) * w2[32 + lane];
#pragma unroll
    for (int o = 16; o; o >>= 1) s += __shfl_xor_sync(0xffffffffu, s, o);
    if (lane == 0) out[n] = s + b2[0];
}

// ---------------------------------------------------------------------------------
extern "C" void kernel_launch(void* const* d_in, const int* in_sizes, int n_in,
                              void* d_out, int out_size) {
    const float* x    = (const float*)d_in[0];
    const int*   ei   = (const int*)d_in[1];
    const float* attr = (const float*)d_in[2];
    const float* ci   = (const float*)d_in[3];
    const float* f1w  = (const float*)d_in[4];
    const float* f1b  = (const float*)d_in[5];
    const float* kw1  = (const float*)d_in[6];
    const float* kb1  = (const float*)d_in[7];
    const float* kw2  = (const float*)d_in[8];
    const float* kb2  = (const float*)d_in[9];
    const float* kw3  = (const float*)d_in[10];
    const float* kb3  = (const float*)d_in[11];
    const float* cw1  = (const float*)d_in[12];
    const float* cb1  = (const float*)d_in[13];
    const float* cw2  = (const float*)d_in[14];
    const float* f2w1 = (const float*)d_in[15];
    const float* f2b1 = (const float*)d_in[16];
    const float* f2w2 = (const float*)d_in[17];
    const float* f2b2 = (const float*)d_in[18];
    float* out = (float*)d_out;

    int w3h_grid = ((NN + 63) / 64) * 16;

    k_prep<<<(NN * 32 + 255) / 256, 256>>>(x, f1w, f1b, ci);   // 0
    k_hist<<<(EE + 255) / 256, 256>>>(ei);                      // 1
    k_scan<<<1, 1024>>>();                                      // 2
    k_w3h_mma<<<w3h_grid, 256>>>(kw3);                          // 3 <- profiled (L0 w3h)
    k_scatter<<<(EE + 255) / 256, 256>>>(ei);                   // 4
    k_edge_mlp<<<(EE + 31) / 32, 256>>>(ei, attr, kw1, kb1, kw2, kb2);  // 5 (L0)
    k_contract<<<(NN + 3) / 4, 128>>>(ei, kb3, cw1, cb1, cw2);          // 6 (L0)
    k_update<<<(NN * 32 + 255) / 256, 256>>>();                         // 7 (L0)

    for (int L = 1; L < 3; L++) {
        k_edge_mlp<<<(EE + 31) / 32, 256>>>(ei, attr, kw1, kb1, kw2, kb2);
        k_w3h_mma<<<w3h_grid, 256>>>(kw3);
        k_contract<<<(NN + 3) / 4, 128>>>(ei, kb3, cw1, cb1, cw2);
        k_update<<<(NN * 32 + 255) / 256, 256>>>();
    }

    k_final<<<(NN * 32 + 255) / 256, 256>>>(f2w1, f2b1, f2w2, f2b2, out);
}

// round 7
// speedup vs baseline: 1.4808x; 1.2457x over previous
#include <cuda_runtime.h>
#include <cuda_fp16.h>

#define NN 10000
#define EE 100000

// ---------------- scratch (static device globals; no allocation) ----------------
__device__ float g_h[NN * 32];
__device__ float g_coord[NN * 3];
__device__ float g_k2[(size_t)EE * 128];
__device__ __align__(16) __half g_W3hH[(size_t)NN * 4096];  // [n][cg:16][i:32][cw:8]
__device__ float g_acch[NN * 32];
__device__ float g_accc[NN * 3];
__device__ int   g_cntc[NN];
__device__ int   g_cntr[NN];
__device__ int   g_fill[NN];
__device__ int   g_cptr[NN + 1];
__device__ int   g_ebc[EE];

__device__ __forceinline__ unsigned f2tf32(float f) {
    unsigned u;
    asm("cvt.rna.tf32.f32 %0, %1;" : "=r"(u) : "f"(f));
    return u;
}
__device__ __forceinline__ void mma_tf32(float& c0, float& c1, float& c2, float& c3,
                                         unsigned a0, unsigned a1, unsigned a2, unsigned a3,
                                         unsigned b0, unsigned b1) {
    asm("mma.sync.aligned.m16n8k8.row.col.f32.tf32.tf32.f32 "
        "{%0,%1,%2,%3}, {%4,%5,%6,%7}, {%8,%9}, {%0,%1,%2,%3};"
        : "+f"(c0), "+f"(c1), "+f"(c2), "+f"(c3)
        : "r"(a0), "r"(a1), "r"(a2), "r"(a3), "r"(b0), "r"(b1));
}
__device__ __forceinline__ float2 h2f2(unsigned u) {
    __half2 h = *reinterpret_cast<__half2*>(&u);
    return __half22float2(h);
}

// ---------------- init ----------------
__global__ void k_prep(const float* __restrict__ x, const float* __restrict__ w,
                       const float* __restrict__ b, const float* __restrict__ ci) {
    int idx = blockIdx.x * blockDim.x + threadIdx.x;
    if (idx < NN * 32) {
        int n = idx >> 5, j = idx & 31;
        float s = b[j];
        s += x[n * 3 + 0] * w[j] + x[n * 3 + 1] * w[32 + j] + x[n * 3 + 2] * w[64 + j];
        g_h[idx] = s;
        g_acch[idx] = 0.f;
    }
    if (idx < NN * 3) { g_coord[idx] = ci[idx]; g_accc[idx] = 0.f; }
    if (idx < NN) { g_cntc[idx] = 0; g_cntr[idx] = 0; g_fill[idx] = 0; }
}

__global__ void k_hist(const int* __restrict__ ei) {
    int e = blockIdx.x * blockDim.x + threadIdx.x;
    if (e < EE) {
        atomicAdd(&g_cntr[ei[e]], 1);
        atomicAdd(&g_cntc[ei[EE + e]], 1);
    }
}

__global__ void k_scan() {
    __shared__ int ss[1024];
    int t = threadIdx.x;
    int base = t * 10;
    int loc[10];
    int s = 0;
#pragma unroll
    for (int i = 0; i < 10; i++) {
        int v = (base + i < NN) ? g_cntc[base + i] : 0;
        loc[i] = s; s += v;
    }
    ss[t] = s;
    __syncthreads();
    for (int off = 1; off < 1024; off <<= 1) {
        int v = (t >= off) ? ss[t - off] : 0;
        __syncthreads();
        ss[t] += v;
        __syncthreads();
    }
    int pre = (t > 0) ? ss[t - 1] : 0;
#pragma unroll
    for (int i = 0; i < 10; i++)
        if (base + i < NN) g_cptr[base + i] = pre + loc[i];
    if (t == 1023) g_cptr[NN] = ss[1023];
}

__global__ void k_scatter(const int* __restrict__ ei) {
    int e = blockIdx.x * blockDim.x + threadIdx.x;
    if (e < EE) {
        int c = ei[EE + e];
        int p = g_cptr[c] + atomicAdd(&g_fill[c], 1);
        g_ebc[p] = e;
    }
}

// -------- edge MLP: k1 scalar, k2 GEMM via single tf32 mma ------------------------
// 64 edges x 128 cols per block, K=64 in two k-halves of 32.
__global__ __launch_bounds__(256) void k_edge_mma(
    const int* __restrict__ ei, const float* __restrict__ attr,
    const float* __restrict__ W1, const float* __restrict__ B1,
    const float* __restrict__ W2, const float* __restrict__ B2) {
    __shared__ unsigned s_w2t[128][36];   // [col][k-half] tf32
    __shared__ unsigned s_k1[64][36];     // [edge][k-half] tf32
    __shared__ float s_kin[64][8];
    __shared__ float s_w1[7 * 64];
    __shared__ float s_b1[64];
    __shared__ float s_b2[128];
    int t = threadIdx.x, warp = t >> 5, lane = t & 31;
    int e0 = blockIdx.x * 64;

    for (int i = t; i < 7 * 64; i += 256) s_w1[i] = W1[i];
    if (t < 64) s_b1[t] = B1[t];
    else if (t < 192) s_b2[t - 64] = B2[t - 64];

    if (t < 64) {
        int e = e0 + t;
        float rad = 0.f;
        if (e < EE) {
            int r = ei[e], c = ei[EE + e];
            float d0 = g_coord[r * 3 + 0] - g_coord[c * 3 + 0];
            float d1 = g_coord[r * 3 + 1] - g_coord[c * 3 + 1];
            float d2 = g_coord[r * 3 + 2] - g_coord[c * 3 + 2];
            rad = d0 * d0 + d1 * d1 + d2 * d2;
#pragma unroll
            for (int q = 0; q < 6; q++) s_kin[t][q] = attr[e * 6 + q];
        } else {
#pragma unroll
            for (int q = 0; q < 6; q++) s_kin[t][q] = 0.f;
        }
        s_kin[t][6] = rad;
        s_kin[t][7] = 0.f;
    }
    __syncthreads();

    int wm = warp & 3, wn = warp >> 2;   // wm: edge group of 16; wn: col half of 64
    int qr = lane >> 2, qc = lane & 3;
    float acc[8][4];
#pragma unroll
    for (int nt = 0; nt < 8; nt++)
#pragma unroll
        for (int j = 0; j < 4; j++) acc[nt][j] = 0.f;

    for (int half = 0; half < 2; half++) {
        // stage W2 k-half as tf32 [col][kk]
        for (int i = t; i < 128 * 32; i += 256) {
            int col = i & 127, kk = i >> 7;
            s_w2t[col][kk] = f2tf32(W2[(half * 32 + kk) * 128 + col]);
        }
        // compute k1 half (scalar) -> tf32 [edge][kk]
        for (int i = t; i < 64 * 32; i += 256) {
            int e = i >> 5, cc = i & 31, c = half * 32 + cc;
            float s = s_b1[c];
#pragma unroll
            for (int q = 0; q < 7; q++) s = fmaf(s_kin[e][q], s_w1[q * 64 + c], s);
            s_k1[e][cc] = f2tf32(fmaxf(s, 0.f));
        }
        __syncthreads();

#pragma unroll
        for (int ks = 0; ks < 4; ks++) {
            int k0 = ks * 8;
            unsigned a0 = s_k1[wm * 16 + qr][k0 + qc];
            unsigned a1 = s_k1[wm * 16 + qr + 8][k0 + qc];
            unsigned a2 = s_k1[wm * 16 + qr][k0 + qc + 4];
            unsigned a3 = s_k1[wm * 16 + qr + 8][k0 + qc + 4];
#pragma unroll
            for (int nt = 0; nt < 8; nt++) {
                int col = wn * 64 + nt * 8;
                unsigned b0 = s_w2t[col + qr][k0 + qc];
                unsigned b1 = s_w2t[col + qr][k0 + qc + 4];
                mma_tf32(acc[nt][0], acc[nt][1], acc[nt][2], acc[nt][3],
                         a0, a1, a2, a3, b0, b1);
            }
        }
        __syncthreads();
    }

    int eA = e0 + wm * 16 + qr, eB = eA + 8;
#pragma unroll
    for (int nt = 0; nt < 8; nt++) {
        int col = wn * 64 + nt * 8 + 2 * qc;
        float bx = s_b2[col], by = s_b2[col + 1];
        if (eA < EE)
            *(float2*)&g_k2[(size_t)eA * 128 + col] =
                make_float2(fmaxf(acc[nt][0] + bx, 0.f), fmaxf(acc[nt][1] + by, 0.f));
        if (eB < EE)
            *(float2*)&g_k2[(size_t)eB * 128 + col] =
                make_float2(fmaxf(acc[nt][2] + bx, 0.f), fmaxf(acc[nt][3] + by, 0.f));
    }
}

// -------- W3h via single tf32 mma -> fp16 chunk-transposed (padded epilogue) ------
struct SmemW3h {
    unsigned a[64][36];
    unsigned b[256][36];
};
__global__ __launch_bounds__(256) void k_w3h_mma(const float* __restrict__ W3) {
    constexpr unsigned SB = sizeof(SmemW3h);   // 46080 > 64*264*2 = 33792
    __shared__ __align__(16) char sb[SB];
    SmemW3h& sm = *(SmemW3h*)sb;
    int t = threadIdx.x, warp = t >> 5, lane = t & 31;
    int cg = blockIdx.x & 15;
    int o0 = cg * 256, n0 = (blockIdx.x >> 4) * 64;

    for (int i = t; i < 64 * 8; i += 256) {
        int n = i >> 3, kq = i & 7;
        float4 v = make_float4(0.f, 0.f, 0.f, 0.f);
        if (n0 + n < NN) v = *(const float4*)&g_h[(n0 + n) * 32 + kq * 4];
        sm.a[n][kq * 4 + 0] = f2tf32(v.x); sm.a[n][kq * 4 + 1] = f2tf32(v.y);
        sm.a[n][kq * 4 + 2] = f2tf32(v.z); sm.a[n][kq * 4 + 3] = f2tf32(v.w);
    }
    for (int i = t; i < 256 * 8; i += 256) {
        int o = i >> 3, kq = i & 7;
        float4 v = *(const float4*)&W3[(size_t)(o0 + o) * 32 + kq * 4];
        sm.b[o][kq * 4 + 0] = f2tf32(v.x); sm.b[o][kq * 4 + 1] = f2tf32(v.y);
        sm.b[o][kq * 4 + 2] = f2tf32(v.z); sm.b[o][kq * 4 + 3] = f2tf32(v.w);
    }
    __syncthreads();

    int wm = warp & 3, wn = warp >> 2;
    int qr = lane >> 2, qc = lane & 3;
    float acc[16][4];
#pragma unroll
    for (int nt = 0; nt < 16; nt++)
#pragma unroll
        for (int j = 0; j < 4; j++) acc[nt][j] = 0.f;

#pragma unroll
    for (int ks = 0; ks < 4; ks++) {
        int k0 = ks * 8;
        unsigned a0 = sm.a[wm * 16 + qr][k0 + qc];
        unsigned a1 = sm.a[wm * 16 + qr + 8][k0 + qc];
        unsigned a2 = sm.a[wm * 16 + qr][k0 + qc + 4];
        unsigned a3 = sm.a[wm * 16 + qr + 8][k0 + qc + 4];
#pragma unroll
        for (int nt = 0; nt < 16; nt++) {
            int ob = wn * 128 + nt * 8;
            unsigned b0 = sm.b[ob + qr][k0 + qc];
            unsigned b1 = sm.b[ob + qr][k0 + qc + 4];
            mma_tf32(acc[nt][0], acc[nt][1], acc[nt][2], acc[nt][3],
                     a0, a1, a2, a3, b0, b1);
        }
    }
    __syncthreads();   // staging dead; reuse as fp16 tile (rows padded to 264 halfs)

    // (nt, nt+4) pairs share one half2 word: same i, cw and cw+1
    __half2* so2 = (__half2*)sb;
    int nlA = wm * 16 + qr, nlB = nlA + 8;
#pragma unroll
    for (int g = 0; g < 8; g++) {
        int nt = (g & 3) + (g >> 2) * 8;   // {0,1,2,3, 8,9,10,11}
#pragma unroll
        for (int j = 0; j < 2; j++) {
            int ol = wn * 128 + nt * 8 + 2 * qc + j;
            int cw = ol >> 5, i = ol & 31;
            int word = i * 4 + (cw >> 1);
            so2[nlA * 132 + word] = __floats2half2_rn(acc[nt][j], acc[nt + 4][j]);
            so2[nlB * 132 + word] = __floats2half2_rn(acc[nt][2 + j], acc[nt + 4][2 + j]);
        }
    }
    __syncthreads();

    // coalesced copy out: 32 uint4 per row (row stride 33 uint4, data in first 32)
    uint4* dst = (uint4*)g_W3hH;
    const uint4* src = (const uint4*)sb;
    for (int r = warp; r < 64; r += 8) {
        int n = n0 + r;
        if (n < NN) dst[(size_t)n * 512 + cg * 32 + lane] = src[r * 33 + lane];
    }
}

// -------- contraction: warp per col-node; W3h row as 16 x uint4 (fp16) ------------
__global__ __launch_bounds__(128) void k_contract(
    const int* __restrict__ ei, const float* __restrict__ B3,
    const float* __restrict__ CW1, const float* __restrict__ CB1,
    const float* __restrict__ CW2) {
    __shared__ float  s_cw1[32][32];
    __shared__ float4 s_k2[4][2][32];
    int t = threadIdx.x, lane = t & 31, w = t >> 5;
    for (int i = t; i < 1024; i += 128) ((float*)s_cw1)[i] = CW1[i];
    __syncthreads();

    int n = blockIdx.x * 4 + w;
    if (n >= NN) return;
    int beg = g_cptr[n], end = g_cptr[n + 1];
    if (beg == end) return;

    uint4 rq[16];
    const uint4* wp = (const uint4*)g_W3hH + (size_t)n * 512 + lane;
#pragma unroll
    for (int cg = 0; cg < 16; cg++) rq[cg] = wp[cg * 32];

    float hv = g_h[n * 32 + lane];
    float bh = 0.f;
#pragma unroll
    for (int j = 0; j < 32; j++)
        bh = fmaf(B3[lane * 32 + j], __shfl_sync(0xffffffffu, hv, j), bh);

    float cc = (lane < 3) ? g_coord[n * 3 + lane] : 0.f;
    float cb1l = CB1[lane], cw2l = CW2[lane];

    int e = g_ebc[beg];
    float4 kq = *(const float4*)(g_k2 + (size_t)e * 128 + lane * 4);
    for (int p = beg; p < end; p++) {
        int buf = p & 1;
        s_k2[w][buf][lane] = kq;
        int ecur = e;
        __syncwarp();
        if (p + 1 < end) {
            e = g_ebc[p + 1];
            kq = *(const float4*)(g_k2 + (size_t)e * 128 + lane * 4);
        }
        int rn = ei[ecur];
        float m0 = bh, m1 = 0.f, m2 = 0.f, m3 = 0.f;
#pragma unroll
        for (int cg = 0; cg < 16; cg++) {
            float4 ka = s_k2[w][buf][2 * cg];
            float4 kb = s_k2[w][buf][2 * cg + 1];
            uint4  q  = rq[cg];
            float2 w0 = h2f2(q.x), w1 = h2f2(q.y), w2 = h2f2(q.z), w3 = h2f2(q.w);
            m0 = fmaf(ka.x, w0.x, m0); m1 = fmaf(ka.y, w0.y, m1);
            m2 = fmaf(ka.z, w1.x, m2); m3 = fmaf(ka.w, w1.y, m3);
            m0 = fmaf(kb.x, w2.x, m0); m1 = fmaf(kb.y, w2.y, m1);
            m2 = fmaf(kb.z, w3.x, m2); m3 = fmaf(kb.w, w3.y, m3);
        }
        float m = (m0 + m1) + (m2 + m3);

        float t0 = cb1l, t1 = 0.f, t2 = 0.f, t3 = 0.f;
#pragma unroll
        for (int i = 0; i < 8; i++) {
            t0 = fmaf(__shfl_sync(0xffffffffu, m, 4 * i + 0), s_cw1[4 * i + 0][lane], t0);
            t1 = fmaf(__shfl_sync(0xffffffffu, m, 4 * i + 1), s_cw1[4 * i + 1][lane], t1);
            t2 = fmaf(__shfl_sync(0xffffffffu, m, 4 * i + 2), s_cw1[4 * i + 2][lane], t2);
            t3 = fmaf(__shfl_sync(0xffffffffu, m, 4 * i + 3), s_cw1[4 * i + 3][lane], t3);
        }
        float tj = fmaxf((t0 + t1) + (t2 + t3), 0.f) * cw2l;
#pragma unroll
        for (int o = 16; o; o >>= 1) tj += __shfl_xor_sync(0xffffffffu, tj, o);

        atomicAdd(&g_acch[rn * 32 + lane], m);
        if (lane < 3)
            atomicAdd(&g_accc[rn * 3 + lane], (g_coord[rn * 3 + lane] - cc) * tj);
    }
}

// ---------------- node update (invc inlined) --------------------------------------
__global__ void k_update() {
    int idx = blockIdx.x * blockDim.x + threadIdx.x;
    if (idx >= NN * 32) return;
    int n = idx >> 5, j = idx & 31;
    int c = g_cntr[n];
    float inv = 1.f / (float)(c > 0 ? c : 1);
    g_h[idx] = fmaxf(g_h[idx] + g_acch[idx] * inv, 0.f);
    g_acch[idx] = 0.f;
    if (j < 3) {
        g_coord[n * 3 + j] += g_accc[n * 3 + j] * inv;
        g_accc[n * 3 + j] = 0.f;
    }
}

// ---------------- final MLP + coord copy ------------------------------------------
__global__ void k_final(const float* __restrict__ w1, const float* __restrict__ b1,
                        const float* __restrict__ w2, const float* __restrict__ b2,
                        float* __restrict__ out) {
    int gid = blockIdx.x * blockDim.x + threadIdx.x;
    if (gid < NN * 3) out[NN + gid] = g_coord[gid];
    int lane = gid & 31;
    int n = gid >> 5;
    if (n >= NN) return;
    float hv = g_h[n * 32 + lane];
    float t0 = b1[lane], t1 = b1[32 + lane];
#pragma unroll
    for (int j = 0; j < 32; j++) {
        float hj = __shfl_sync(0xffffffffu, hv, j);
        t0 = fmaf(hj, w1[j * 64 + lane], t0);
        t1 = fmaf(hj, w1[j * 64 + 32 + lane], t1);
    }
    float s = fmaxf(t0, 0.f) * w2[lane] + fmaxf(t1, 0.f) * w2[32 + lane];
#pragma unroll
    for (int o = 16; o; o >>= 1) s += __shfl_xor_sync(0xffffffffu, s, o);
    if (lane == 0) out[n] = s + b2[0];
}

// ---------------------------------------------------------------------------------
extern "C" void kernel_launch(void* const* d_in, const int* in_sizes, int n_in,
                              void* d_out, int out_size) {
    const float* x    = (const float*)d_in[0];
    const int*   ei   = (const int*)d_in[1];
    const float* attr = (const float*)d_in[2];
    const float* ci   = (const float*)d_in[3];
    const float* f1w  = (const float*)d_in[4];
    const float* f1b  = (const float*)d_in[5];
    const float* kw1  = (const float*)d_in[6];
    const float* kb1  = (const float*)d_in[7];
    const float* kw2  = (const float*)d_in[8];
    const float* kb2  = (const float*)d_in[9];
    const float* kw3  = (const float*)d_in[10];
    const float* kb3  = (const float*)d_in[11];
    const float* cw1  = (const float*)d_in[12];
    const float* cb1  = (const float*)d_in[13];
    const float* cw2  = (const float*)d_in[14];
    const float* f2w1 = (const float*)d_in[15];
    const float* f2b1 = (const float*)d_in[16];
    const float* f2w2 = (const float*)d_in[17];
    const float* f2b2 = (const float*)d_in[18];
    float* out = (float*)d_out;

    int w3h_grid = ((NN + 63) / 64) * 16;
    int edge_grid = (EE + 63) / 64;

    k_prep<<<(NN * 32 + 255) / 256, 256>>>(x, f1w, f1b, ci);            // 0
    k_hist<<<(EE + 255) / 256, 256>>>(ei);                               // 1
    k_scan<<<1, 1024>>>();                                               // 2
    k_edge_mma<<<edge_grid, 256>>>(ei, attr, kw1, kb1, kw2, kb2);        // 3 <- profiled
    k_scatter<<<(EE + 255) / 256, 256>>>(ei);                            // 4
    k_w3h_mma<<<w3h_grid, 256>>>(kw3);                                   // 5 (L0)
    k_contract<<<(NN + 3) / 4, 128>>>(ei, kb3, cw1, cb1, cw2);           // 6 (L0)
    k_update<<<(NN * 32 + 255) / 256, 256>>>();                          // 7 (L0)

    for (int L = 1; L < 3; L++) {
        k_edge_mma<<<edge_grid, 256>>>(ei, attr, kw1, kb1, kw2, kb2);
        k_w3h_mma<<<w3h_grid, 256>>>(kw3);
        k_contract<<<(NN + 3) / 4, 128>>>(ei, kb3, cw1, cb1, cw2);
        k_update<<<(NN * 32 + 255) / 256, 256>>>();
    }

    k_final<<<(NN * 32 + 255) / 256, 256>>>(f2w1, f2b1, f2w2, f2b2, out);
}

// round 8
// speedup vs baseline: 1.5998x; 1.0804x over previous
#include <cuda_runtime.h>
#include <cuda_fp16.h>

#define NN 10000
#define EE 100000

// ---------------- scratch (static device globals; no allocation) ----------------
__device__ float g_h[NN * 32];
__device__ float g_coord[NN * 3];
__device__ __align__(16) __half g_k2h[(size_t)EE * 128];
__device__ unsigned g_W3hB[(size_t)NN * 2048];   // [n][frag:64][lane:32] half2 words
__device__ float g_acch[NN * 32];
__device__ float g_accc[NN * 3];
__device__ int   g_cntc[NN];
__device__ int   g_cntr[NN];
__device__ int   g_fill[NN];
__device__ int   g_cptr[NN + 1];
__device__ int   g_ebc[EE];

__device__ __forceinline__ unsigned f2tf32(float f) {
    unsigned u;
    asm("cvt.rna.tf32.f32 %0, %1;" : "=r"(u) : "f"(f));
    return u;
}
__device__ __forceinline__ void mma_tf32(float& c0, float& c1, float& c2, float& c3,
                                         unsigned a0, unsigned a1, unsigned a2, unsigned a3,
                                         unsigned b0, unsigned b1) {
    asm("mma.sync.aligned.m16n8k8.row.col.f32.tf32.tf32.f32 "
        "{%0,%1,%2,%3}, {%4,%5,%6,%7}, {%8,%9}, {%0,%1,%2,%3};"
        : "+f"(c0), "+f"(c1), "+f"(c2), "+f"(c3)
        : "r"(a0), "r"(a1), "r"(a2), "r"(a3), "r"(b0), "r"(b1));
}
__device__ __forceinline__ void mma_f16(float& c0, float& c1, float& c2, float& c3,
                                        unsigned a0, unsigned a1, unsigned a2, unsigned a3,
                                        unsigned b0, unsigned b1) {
    asm("mma.sync.aligned.m16n8k16.row.col.f32.f16.f16.f32 "
        "{%0,%1,%2,%3}, {%4,%5,%6,%7}, {%8,%9}, {%0,%1,%2,%3};"
        : "+f"(c0), "+f"(c1), "+f"(c2), "+f"(c3)
        : "r"(a0), "r"(a1), "r"(a2), "r"(a3), "r"(b0), "r"(b1));
}

// ---------------- init ----------------
__global__ void k_prep(const float* __restrict__ x, const float* __restrict__ w,
                       const float* __restrict__ b, const float* __restrict__ ci) {
    int idx = blockIdx.x * blockDim.x + threadIdx.x;
    if (idx < NN * 32) {
        int n = idx >> 5, j = idx & 31;
        float s = b[j];
        s += x[n * 3 + 0] * w[j] + x[n * 3 + 1] * w[32 + j] + x[n * 3 + 2] * w[64 + j];
        g_h[idx] = s;
        g_acch[idx] = 0.f;
    }
    if (idx < NN * 3) { g_coord[idx] = ci[idx]; g_accc[idx] = 0.f; }
    if (idx < NN) { g_cntc[idx] = 0; g_cntr[idx] = 0; g_fill[idx] = 0; }
}

__global__ void k_hist(const int* __restrict__ ei) {
    int e = blockIdx.x * blockDim.x + threadIdx.x;
    if (e < EE) {
        atomicAdd(&g_cntr[ei[e]], 1);
        atomicAdd(&g_cntc[ei[EE + e]], 1);
    }
}

__global__ void k_scan() {
    __shared__ int ss[1024];
    int t = threadIdx.x;
    int base = t * 10;
    int loc[10];
    int s = 0;
#pragma unroll
    for (int i = 0; i < 10; i++) {
        int v = (base + i < NN) ? g_cntc[base + i] : 0;
        loc[i] = s; s += v;
    }
    ss[t] = s;
    __syncthreads();
    for (int off = 1; off < 1024; off <<= 1) {
        int v = (t >= off) ? ss[t - off] : 0;
        __syncthreads();
        ss[t] += v;
        __syncthreads();
    }
    int pre = (t > 0) ? ss[t - 1] : 0;
#pragma unroll
    for (int i = 0; i < 10; i++)
        if (base + i < NN) g_cptr[base + i] = pre + loc[i];
    if (t == 1023) g_cptr[NN] = ss[1023];
}

__global__ void k_scatter(const int* __restrict__ ei) {
    int e = blockIdx.x * blockDim.x + threadIdx.x;
    if (e < EE) {
        int c = ei[EE + e];
        int p = g_cptr[c] + atomicAdd(&g_fill[c], 1);
        g_ebc[p] = e;
    }
}

// -------- edge MLP: k1 scalar, k2 via 2-mma tf32 (A hi/lo split), fp16 output -----
__global__ __launch_bounds__(256) void k_edge_mma(
    const int* __restrict__ ei, const float* __restrict__ attr,
    const float* __restrict__ W1, const float* __restrict__ B1,
    const float* __restrict__ W2, const float* __restrict__ B2) {
    __shared__ unsigned s_w2t[128][36];   // [col][kk] tf32
    __shared__ unsigned s_k1h[64][36];    // [edge][kk] tf32 hi
    __shared__ unsigned s_k1l[64][36];    // [edge][kk] tf32 lo
    __shared__ float s_kin[64][8];
    __shared__ float s_w1[7 * 64];
    __shared__ float s_b1[64];
    __shared__ float s_b2[128];
    int t = threadIdx.x, warp = t >> 5, lane = t & 31;
    int e0 = blockIdx.x * 64;

    for (int i = t; i < 7 * 64; i += 256) s_w1[i] = W1[i];
    if (t < 64) s_b1[t] = B1[t];
    else if (t < 192) s_b2[t - 64] = B2[t - 64];

    if (t < 64) {
        int e = e0 + t;
        float rad = 0.f;
        if (e < EE) {
            int r = ei[e], c = ei[EE + e];
            float d0 = g_coord[r * 3 + 0] - g_coord[c * 3 + 0];
            float d1 = g_coord[r * 3 + 1] - g_coord[c * 3 + 1];
            float d2 = g_coord[r * 3 + 2] - g_coord[c * 3 + 2];
            rad = d0 * d0 + d1 * d1 + d2 * d2;
#pragma unroll
            for (int q = 0; q < 6; q++) s_kin[t][q] = attr[e * 6 + q];
        } else {
#pragma unroll
            for (int q = 0; q < 6; q++) s_kin[t][q] = 0.f;
        }
        s_kin[t][6] = rad;
        s_kin[t][7] = 0.f;
    }
    __syncthreads();

    int wm = warp & 3, wn = warp >> 2;
    int qr = lane >> 2, qc = lane & 3;
    float acc[8][4];
#pragma unroll
    for (int nt = 0; nt < 8; nt++)
#pragma unroll
        for (int j = 0; j < 4; j++) acc[nt][j] = 0.f;

    for (int half = 0; half < 2; half++) {
        for (int i = t; i < 128 * 32; i += 256) {
            int col = i & 127, kk = i >> 7;
            s_w2t[col][kk] = f2tf32(W2[(half * 32 + kk) * 128 + col]);
        }
        for (int i = t; i < 64 * 32; i += 256) {
            int e = i >> 5, cc = i & 31, c = half * 32 + cc;
            float s = s_b1[c];
#pragma unroll
            for (int q = 0; q < 7; q++) s = fmaf(s_kin[e][q], s_w1[q * 64 + c], s);
            s = fmaxf(s, 0.f);
            unsigned hi = f2tf32(s);
            s_k1h[e][cc] = hi;
            s_k1l[e][cc] = f2tf32(s - __uint_as_float(hi));
        }
        __syncthreads();

#pragma unroll
        for (int ks = 0; ks < 4; ks++) {
            int k0 = ks * 8;
            unsigned ah0 = s_k1h[wm * 16 + qr][k0 + qc];
            unsigned ah1 = s_k1h[wm * 16 + qr + 8][k0 + qc];
            unsigned ah2 = s_k1h[wm * 16 + qr][k0 + qc + 4];
            unsigned ah3 = s_k1h[wm * 16 + qr + 8][k0 + qc + 4];
            unsigned al0 = s_k1l[wm * 16 + qr][k0 + qc];
            unsigned al1 = s_k1l[wm * 16 + qr + 8][k0 + qc];
            unsigned al2 = s_k1l[wm * 16 + qr][k0 + qc + 4];
            unsigned al3 = s_k1l[wm * 16 + qr + 8][k0 + qc + 4];
#pragma unroll
            for (int nt = 0; nt < 8; nt++) {
                int col = wn * 64 + nt * 8;
                unsigned b0 = s_w2t[col + qr][k0 + qc];
                unsigned b1 = s_w2t[col + qr][k0 + qc + 4];
                mma_tf32(acc[nt][0], acc[nt][1], acc[nt][2], acc[nt][3],
                         ah0, ah1, ah2, ah3, b0, b1);
                mma_tf32(acc[nt][0], acc[nt][1], acc[nt][2], acc[nt][3],
                         al0, al1, al2, al3, b0, b1);
            }
        }
        __syncthreads();
    }

    int eA = e0 + wm * 16 + qr, eB = eA + 8;
#pragma unroll
    for (int nt = 0; nt < 8; nt++) {
        int col = wn * 64 + nt * 8 + 2 * qc;
        float bx = s_b2[col], by = s_b2[col + 1];
        if (eA < EE)
            *(__half2*)&g_k2h[(size_t)eA * 128 + col] =
                __floats2half2_rn(fmaxf(acc[nt][0] + bx, 0.f), fmaxf(acc[nt][1] + by, 0.f));
        if (eB < EE)
            *(__half2*)&g_k2h[(size_t)eB * 128 + col] =
                __floats2half2_rn(fmaxf(acc[nt][2] + bx, 0.f), fmaxf(acc[nt][3] + by, 0.f));
    }
}

// -------- W3h via tf32 mma -> fp16 in B-fragment order ----------------------------
// B layout: word(n, f, l) at n*2048 + f*32 + l; f = (ks*4 + nt_b)*2 + par;
// word = half2{W3h[c][i], W3h[c+1][i]}, c = ks*16 + par*8 + 2*(l&3), i = nt_b*8 + (l>>2).
struct SmemW3h {
    unsigned a[64][36];
    unsigned b[256][36];
};
__global__ __launch_bounds__(256) void k_w3h_mma(const float* __restrict__ W3) {
    constexpr unsigned SB = sizeof(SmemW3h);   // 46080 > 64*132*4 = 33792
    __shared__ __align__(16) char sb[SB];
    SmemW3h& sm = *(SmemW3h*)sb;
    int t = threadIdx.x, warp = t >> 5, lane = t & 31;
    int cg = blockIdx.x & 15;
    int o0 = cg * 256, n0 = (blockIdx.x >> 4) * 64;

    for (int i = t; i < 64 * 8; i += 256) {
        int n = i >> 3, kq = i & 7;
        float4 v = make_float4(0.f, 0.f, 0.f, 0.f);
        if (n0 + n < NN) v = *(const float4*)&g_h[(n0 + n) * 32 + kq * 4];
        sm.a[n][kq * 4 + 0] = f2tf32(v.x); sm.a[n][kq * 4 + 1] = f2tf32(v.y);
        sm.a[n][kq * 4 + 2] = f2tf32(v.z); sm.a[n][kq * 4 + 3] = f2tf32(v.w);
    }
    for (int i = t; i < 256 * 8; i += 256) {
        int o = i >> 3, kq = i & 7;
        float4 v = *(const float4*)&W3[(size_t)(o0 + o) * 32 + kq * 4];
        sm.b[o][kq * 4 + 0] = f2tf32(v.x); sm.b[o][kq * 4 + 1] = f2tf32(v.y);
        sm.b[o][kq * 4 + 2] = f2tf32(v.z); sm.b[o][kq * 4 + 3] = f2tf32(v.w);
    }
    __syncthreads();

    int wm = warp & 3, wn = warp >> 2;
    int qr = lane >> 2, qc = lane & 3;
    float acc[16][4];
#pragma unroll
    for (int nt = 0; nt < 16; nt++)
#pragma unroll
        for (int j = 0; j < 4; j++) acc[nt][j] = 0.f;

#pragma unroll
    for (int ks = 0; ks < 4; ks++) {
        int k0 = ks * 8;
        unsigned a0 = sm.a[wm * 16 + qr][k0 + qc];
        unsigned a1 = sm.a[wm * 16 + qr + 8][k0 + qc];
        unsigned a2 = sm.a[wm * 16 + qr][k0 + qc + 4];
        unsigned a3 = sm.a[wm * 16 + qr + 8][k0 + qc + 4];
#pragma unroll
        for (int nt = 0; nt < 16; nt++) {
            int ob = wn * 128 + nt * 8;
            unsigned b0 = sm.b[ob + qr][k0 + qc];
            unsigned b1 = sm.b[ob + qr][k0 + qc + 4];
            mma_tf32(acc[nt][0], acc[nt][1], acc[nt][2], acc[nt][3],
                     a0, a1, a2, a3, b0, b1);
        }
    }
    __syncthreads();   // staging dead; reuse as half2 tile (64 rows x 132 words)

    unsigned* so = (unsigned*)sb;
    int nlA = wm * 16 + qr, nlB = nlA + 8;
#pragma unroll
    for (int g = 0; g < 8; g++) {
        int ntA = (g & 3) + (g >> 2) * 8;
#pragma unroll
        for (int j = 0; j < 2; j++) {
            // i = (g&3)*8 + 2qc + j; cp = wn*2 + (g>>2); w = (g&3)*32 + (2qc+j)*4 + cp
            int w = (g & 3) * 32 + (2 * qc + j) * 4 + wn * 2 + (g >> 2);
            __half2 vA = __floats2half2_rn(acc[ntA][j], acc[ntA + 4][j]);
            __half2 vB = __floats2half2_rn(acc[ntA][2 + j], acc[ntA + 4][2 + j]);
            so[nlA * 132 + w] = *(unsigned*)&vA;
            so[nlB * 132 + w] = *(unsigned*)&vB;
        }
    }
    __syncthreads();

    int ks = cg >> 1, par = cg & 1;
    for (int r = warp; r < 64; r += 8) {
        int n = n0 + r;
        if (n < NN) {
#pragma unroll
            for (int ch = 0; ch < 4; ch++)
                g_W3hB[(size_t)n * 2048 + ks * 256 + ch * 64 + par * 32 + lane] =
                    so[r * 132 + ch * 32 + lane];
        }
    }
}

// -------- contraction via fp16 mma: warp per node, 16-edge groups -----------------
__global__ __launch_bounds__(128) void k_contract_mma(
    const int* __restrict__ ei, const float* __restrict__ B3,
    const float* __restrict__ CW1, const float* __restrict__ CB1,
    const float* __restrict__ CW2) {
    __shared__ float  s_cw1[32][33];
    __shared__ __half s_a[4][16][136];
    __shared__ float  s_m[4][16][33];
    __shared__ int    s_e[4][16];
    __shared__ int    s_rn[4][16];
    int t = threadIdx.x, lane = t & 31, w = t >> 5;
    for (int i = t; i < 1024; i += 128) s_cw1[i >> 5][i & 31] = CW1[i];
    __syncthreads();

    int n = blockIdx.x * 4 + w;
    if (n >= NN) return;
    int beg = g_cptr[n], end = g_cptr[n + 1];
    if (beg == end) return;

    int qr = lane >> 2, qc = lane & 3;

    // B fragments: 64 coalesced 128B lines
    unsigned u[64];
    const unsigned* bp = g_W3hB + (size_t)n * 2048 + lane;
#pragma unroll
    for (int f = 0; f < 64; f++) u[f] = bp[f * 32];

    // bias terms
    float hv = g_h[n * 32 + lane];
    float bh = 0.f;
#pragma unroll
    for (int j = 0; j < 32; j++)
        bh = fmaf(B3[lane * 32 + j], __shfl_sync(0xffffffffu, hv, j), bh);
    float bterm = CB1[lane];
#pragma unroll
    for (int j = 0; j < 32; j++)
        bterm = fmaf(__shfl_sync(0xffffffffu, bh, j), s_cw1[j][lane], bterm);

    float cc = (lane < 3) ? g_coord[n * 3 + lane] : 0.f;
    float cw2l = CW2[lane];

    for (int g0 = beg; g0 < end; g0 += 16) {
        int gsz = min(16, end - g0);
        if (lane < 16) {
            int e = (lane < gsz) ? g_ebc[g0 + lane] : g_ebc[g0];
            s_e[w][lane] = e;
            s_rn[w][lane] = ei[e];
        }
        __syncwarp();
        // stage k2 rows (fp16): 256 uint4, coalesced per row
#pragma unroll
        for (int it = 0; it < 8; it++) {
            int idx = it * 32 + lane;
            int row = idx >> 4, part = idx & 15;
            ((uint4*)&s_a[w][row][0])[part] =
                ((const uint4*)(g_k2h + (size_t)s_e[w][row] * 128))[part];
        }
        __syncwarp();

        float acc[4][4];
#pragma unroll
        for (int nt = 0; nt < 4; nt++)
#pragma unroll
            for (int j = 0; j < 4; j++) acc[nt][j] = 0.f;

#pragma unroll
        for (int ks = 0; ks < 8; ks++) {
            int k0 = ks * 16 + 2 * qc;
            unsigned a0 = *(const unsigned*)&s_a[w][qr][k0];
            unsigned a1 = *(const unsigned*)&s_a[w][qr + 8][k0];
            unsigned a2 = *(const unsigned*)&s_a[w][qr][k0 + 8];
            unsigned a3 = *(const unsigned*)&s_a[w][qr + 8][k0 + 8];
#pragma unroll
            for (int nt = 0; nt < 4; nt++)
                mma_f16(acc[nt][0], acc[nt][1], acc[nt][2], acc[nt][3],
                        a0, a1, a2, a3, u[(ks * 4 + nt) * 2], u[(ks * 4 + nt) * 2 + 1]);
        }
        __syncwarp();
#pragma unroll
        for (int nt = 0; nt < 4; nt++) {
#pragma unroll
            for (int j = 0; j < 2; j++) {
                s_m[w][qr][nt * 8 + 2 * qc + j] = acc[nt][j];
                s_m[w][qr + 8][nt * 8 + 2 * qc + j] = acc[nt][2 + j];
            }
        }
        __syncwarp();

        for (int r = 0; r < gsz; r++) {
            int rn = s_rn[w][r];
            float mi = s_m[w][r][lane] + bh;
            float t0 = bterm, t1 = 0.f, t2 = 0.f, t3 = 0.f;
#pragma unroll
            for (int j = 0; j < 8; j++) {
                t0 = fmaf(s_m[w][r][4 * j + 0], s_cw1[4 * j + 0][lane], t0);
                t1 = fmaf(s_m[w][r][4 * j + 1], s_cw1[4 * j + 1][lane], t1);
                t2 = fmaf(s_m[w][r][4 * j + 2], s_cw1[4 * j + 2][lane], t2);
                t3 = fmaf(s_m[w][r][4 * j + 3], s_cw1[4 * j + 3][lane], t3);
            }
            float tj = fmaxf((t0 + t1) + (t2 + t3), 0.f) * cw2l;
#pragma unroll
            for (int o = 16; o; o >>= 1) tj += __shfl_xor_sync(0xffffffffu, tj, o);

            atomicAdd(&g_acch[rn * 32 + lane], mi);
            if (lane < 3)
                atomicAdd(&g_accc[rn * 3 + lane], (g_coord[rn * 3 + lane] - cc) * tj);
        }
    }
}

// ---------------- node update (invc inlined) --------------------------------------
__global__ void k_update() {
    int idx = blockIdx.x * blockDim.x + threadIdx.x;
    if (idx >= NN * 32) return;
    int n = idx >> 5, j = idx & 31;
    int c = g_cntr[n];
    float inv = 1.f / (float)(c > 0 ? c : 1);
    g_h[idx] = fmaxf(g_h[idx] + g_acch[idx] * inv, 0.f);
    g_acch[idx] = 0.f;
    if (j < 3) {
        g_coord[n * 3 + j] += g_accc[n * 3 + j] * inv;
        g_accc[n * 3 + j] = 0.f;
    }
}

// ---------------- final MLP + coord copy ------------------------------------------
__global__ void k_final(const float* __restrict__ w1, const float* __restrict__ b1,
                        const float* __restrict__ w2, const float* __restrict__ b2,
                        float* __restrict__ out) {
    int gid = blockIdx.x * blockDim.x + threadIdx.x;
    if (gid < NN * 3) out[NN + gid] = g_coord[gid];
    int lane = gid & 31;
    int n = gid >> 5;
    if (n >= NN) return;
    float hv = g_h[n * 32 + lane];
    float t0 = b1[lane], t1 = b1[32 + lane];
#pragma unroll
    for (int j = 0; j < 32; j++) {
        float hj = __shfl_sync(0xffffffffu, hv, j);
        t0 = fmaf(hj, w1[j * 64 + lane], t0);
        t1 = fmaf(hj, w1[j * 64 + 32 + lane], t1);
    }
    float s = fmaxf(t0, 0.f) * w2[lane] + fmaxf(t1, 0.f) * w2[32 + lane];
#pragma unroll
    for (int o = 16; o; o >>= 1) s += __shfl_xor_sync(0xffffffffu, s, o);
    if (lane == 0) out[n] = s + b2[0];
}

// ---------------------------------------------------------------------------------
extern "C" void kernel_launch(void* const* d_in, const int* in_sizes, int n_in,
                              void* d_out, int out_size) {
    const float* x    = (const float*)d_in[0];
    const int*   ei   = (const int*)d_in[1];
    const float* attr = (const float*)d_in[2];
    const float* ci   = (const float*)d_in[3];
    const float* f1w  = (const float*)d_in[4];
    const float* f1b  = (const float*)d_in[5];
    const float* kw1  = (const float*)d_in[6];
    const float* kb1  = (const float*)d_in[7];
    const float* kw2  = (const float*)d_in[8];
    const float* kb2  = (const float*)d_in[9];
    const float* kw3  = (const float*)d_in[10];
    const float* kb3  = (const float*)d_in[11];
    const float* cw1  = (const float*)d_in[12];
    const float* cb1  = (const float*)d_in[13];
    const float* cw2  = (const float*)d_in[14];
    const float* f2w1 = (const float*)d_in[15];
    const float* f2b1 = (const float*)d_in[16];
    const float* f2w2 = (const float*)d_in[17];
    const float* f2b2 = (const float*)d_in[18];
    float* out = (float*)d_out;

    int w3h_grid = ((NN + 63) / 64) * 16;
    int edge_grid = (EE + 63) / 64;

    k_prep<<<(NN * 32 + 255) / 256, 256>>>(x, f1w, f1b, ci);            // 0
    k_hist<<<(EE + 255) / 256, 256>>>(ei);                               // 1
    k_scan<<<1, 1024>>>();                                               // 2
    k_w3h_mma<<<w3h_grid, 256>>>(kw3);                                   // 3 <- profiled
    k_scatter<<<(EE + 255) / 256, 256>>>(ei);                            // 4
    k_edge_mma<<<edge_grid, 256>>>(ei, attr, kw1, kb1, kw2, kb2);        // 5 (L0)
    k_contract_mma<<<(NN + 3) / 4, 128>>>(ei, kb3, cw1, cb1, cw2);       // 6 (L0)
    k_update<<<(NN * 32 + 255) / 256, 256>>>();                          // 7 (L0)

    for (int L = 1; L < 3; L++) {
        k_edge_mma<<<edge_grid, 256>>>(ei, attr, kw1, kb1, kw2, kb2);
        k_w3h_mma<<<w3h_grid, 256>>>(kw3);
        k_contract_mma<<<(NN + 3) / 4, 128>>>(ei, kb3, cw1, cb1, cw2);
        k_update<<<(NN * 32 + 255) / 256, 256>>>();
    }

    k_final<<<(NN * 32 + 255) / 256, 256>>>(f2w1, f2b1, f2w2, f2b2, out);
}

// round 9
// speedup vs baseline: 1.9745x; 1.2342x over previous
#include <cuda_runtime.h>
#include <cuda_fp16.h>

#define NN 10000
#define EE 100000

// ---------------- scratch (static device globals; no allocation) ----------------
__device__ float g_h[NN * 32];
__device__ float g_coord[NN * 3];
__device__ __align__(16) __half g_k2h[(size_t)EE * 128];
__device__ unsigned g_W3hB[(size_t)NN * 2048];   // [n][frag:64][lane:32] half2 words
__device__ float g_acch[NN * 32];
__device__ float g_accc[NN * 3];
__device__ int   g_cntc[NN];
__device__ int   g_cntr[NN];
__device__ int   g_fill[NN];
__device__ int   g_cptr[NN + 1];
__device__ int   g_ebc[EE];

__device__ __forceinline__ unsigned f2tf32(float f) {
    unsigned u;
    asm("cvt.rna.tf32.f32 %0, %1;" : "=r"(u) : "f"(f));
    return u;
}
__device__ __forceinline__ void mma_tf32(float& c0, float& c1, float& c2, float& c3,
                                         unsigned a0, unsigned a1, unsigned a2, unsigned a3,
                                         unsigned b0, unsigned b1) {
    asm("mma.sync.aligned.m16n8k8.row.col.f32.tf32.tf32.f32 "
        "{%0,%1,%2,%3}, {%4,%5,%6,%7}, {%8,%9}, {%0,%1,%2,%3};"
        : "+f"(c0), "+f"(c1), "+f"(c2), "+f"(c3)
        : "r"(a0), "r"(a1), "r"(a2), "r"(a3), "r"(b0), "r"(b1));
}
__device__ __forceinline__ void mma_f16(float& c0, float& c1, float& c2, float& c3,
                                        unsigned a0, unsigned a1, unsigned a2, unsigned a3,
                                        unsigned b0, unsigned b1) {
    asm("mma.sync.aligned.m16n8k16.row.col.f32.f16.f16.f32 "
        "{%0,%1,%2,%3}, {%4,%5,%6,%7}, {%8,%9}, {%0,%1,%2,%3};"
        : "+f"(c0), "+f"(c1), "+f"(c2), "+f"(c3)
        : "r"(a0), "r"(a1), "r"(a2), "r"(a3), "r"(b0), "r"(b1));
}
__device__ __forceinline__ unsigned packh2(float a, float b) {
    __half2 h = __floats2half2_rn(a, b);
    return *(unsigned*)&h;
}

// ---------------- init ----------------
__global__ void k_prep(const float* __restrict__ x, const float* __restrict__ w,
                       const float* __restrict__ b, const float* __restrict__ ci) {
    int idx = blockIdx.x * blockDim.x + threadIdx.x;
    if (idx < NN * 32) {
        int n = idx >> 5, j = idx & 31;
        float s = b[j];
        s += x[n * 3 + 0] * w[j] + x[n * 3 + 1] * w[32 + j] + x[n * 3 + 2] * w[64 + j];
        g_h[idx] = s;
        g_acch[idx] = 0.f;
    }
    if (idx < NN * 3) { g_coord[idx] = ci[idx]; g_accc[idx] = 0.f; }
    if (idx < NN) { g_cntc[idx] = 0; g_cntr[idx] = 0; g_fill[idx] = 0; }
}

__global__ void k_hist(const int* __restrict__ ei) {
    int e = blockIdx.x * blockDim.x + threadIdx.x;
    if (e < EE) {
        atomicAdd(&g_cntr[ei[e]], 1);
        atomicAdd(&g_cntc[ei[EE + e]], 1);
    }
}

__global__ void k_scan() {
    __shared__ int ss[1024];
    int t = threadIdx.x;
    int base = t * 10;
    int loc[10];
    int s = 0;
#pragma unroll
    for (int i = 0; i < 10; i++) {
        int v = (base + i < NN) ? g_cntc[base + i] : 0;
        loc[i] = s; s += v;
    }
    ss[t] = s;
    __syncthreads();
    for (int off = 1; off < 1024; off <<= 1) {
        int v = (t >= off) ? ss[t - off] : 0;
        __syncthreads();
        ss[t] += v;
        __syncthreads();
    }
    int pre = (t > 0) ? ss[t - 1] : 0;
#pragma unroll
    for (int i = 0; i < 10; i++)
        if (base + i < NN) g_cptr[base + i] = pre + loc[i];
    if (t == 1023) g_cptr[NN] = ss[1023];
}

__global__ void k_scatter(const int* __restrict__ ei) {
    int e = blockIdx.x * blockDim.x + threadIdx.x;
    if (e < EE) {
        int c = ei[EE + e];
        int p = g_cptr[c] + atomicAdd(&g_fill[c], 1);
        g_ebc[p] = e;
    }
}

// -------- edge MLP: k1 scalar, k2 via single tf32 mma, fp16 output ----------------
__global__ __launch_bounds__(256) void k_edge_mma(
    const int* __restrict__ ei, const float* __restrict__ attr,
    const float* __restrict__ W1, const float* __restrict__ B1,
    const float* __restrict__ W2, const float* __restrict__ B2) {
    __shared__ unsigned s_w2t[128][36];   // [col][kk] tf32
    __shared__ unsigned s_k1[64][36];     // [edge][kk] tf32
    __shared__ float s_kin[64][8];
    __shared__ float s_w1[7 * 64];
    __shared__ float s_b1[64];
    __shared__ float s_b2[128];
    int t = threadIdx.x, warp = t >> 5, lane = t & 31;
    int e0 = blockIdx.x * 64;

    for (int i = t; i < 7 * 64; i += 256) s_w1[i] = W1[i];
    if (t < 64) s_b1[t] = B1[t];
    else if (t < 192) s_b2[t - 64] = B2[t - 64];

    if (t < 64) {
        int e = e0 + t;
        float rad = 0.f;
        if (e < EE) {
            int r = ei[e], c = ei[EE + e];
            float d0 = g_coord[r * 3 + 0] - g_coord[c * 3 + 0];
            float d1 = g_coord[r * 3 + 1] - g_coord[c * 3 + 1];
            float d2 = g_coord[r * 3 + 2] - g_coord[c * 3 + 2];
            rad = d0 * d0 + d1 * d1 + d2 * d2;
#pragma unroll
            for (int q = 0; q < 6; q++) s_kin[t][q] = attr[e * 6 + q];
        } else {
#pragma unroll
            for (int q = 0; q < 6; q++) s_kin[t][q] = 0.f;
        }
        s_kin[t][6] = rad;
        s_kin[t][7] = 0.f;
    }
    __syncthreads();

    int wm = warp & 3, wn = warp >> 2;
    int qr = lane >> 2, qc = lane & 3;
    float acc[8][4];
#pragma unroll
    for (int nt = 0; nt < 8; nt++)
#pragma unroll
        for (int j = 0; j < 4; j++) acc[nt][j] = 0.f;

    for (int half = 0; half < 2; half++) {
        for (int i = t; i < 128 * 32; i += 256) {
            int col = i & 127, kk = i >> 7;
            s_w2t[col][kk] = f2tf32(W2[(half * 32 + kk) * 128 + col]);
        }
        for (int i = t; i < 64 * 32; i += 256) {
            int e = i >> 5, cc = i & 31, c = half * 32 + cc;
            float s = s_b1[c];
#pragma unroll
            for (int q = 0; q < 7; q++) s = fmaf(s_kin[e][q], s_w1[q * 64 + c], s);
            s_k1[e][cc] = f2tf32(fmaxf(s, 0.f));
        }
        __syncthreads();

#pragma unroll
        for (int ks = 0; ks < 4; ks++) {
            int k0 = ks * 8;
            unsigned a0 = s_k1[wm * 16 + qr][k0 + qc];
            unsigned a1 = s_k1[wm * 16 + qr + 8][k0 + qc];
            unsigned a2 = s_k1[wm * 16 + qr][k0 + qc + 4];
            unsigned a3 = s_k1[wm * 16 + qr + 8][k0 + qc + 4];
#pragma unroll
            for (int nt = 0; nt < 8; nt++) {
                int col = wn * 64 + nt * 8;
                unsigned b0 = s_w2t[col + qr][k0 + qc];
                unsigned b1 = s_w2t[col + qr][k0 + qc + 4];
                mma_tf32(acc[nt][0], acc[nt][1], acc[nt][2], acc[nt][3],
                         a0, a1, a2, a3, b0, b1);
            }
        }
        __syncthreads();
    }

    int eA = e0 + wm * 16 + qr, eB = eA + 8;
#pragma unroll
    for (int nt = 0; nt < 8; nt++) {
        int col = wn * 64 + nt * 8 + 2 * qc;
        float bx = s_b2[col], by = s_b2[col + 1];
        if (eA < EE)
            *(__half2*)&g_k2h[(size_t)eA * 128 + col] =
                __floats2half2_rn(fmaxf(acc[nt][0] + bx, 0.f), fmaxf(acc[nt][1] + by, 0.f));
        if (eB < EE)
            *(__half2*)&g_k2h[(size_t)eB * 128 + col] =
                __floats2half2_rn(fmaxf(acc[nt][2] + bx, 0.f), fmaxf(acc[nt][3] + by, 0.f));
    }
}

// -------- W3h via tf32 mma -> fp16 in B-fragment order (unchanged from R8) --------
struct SmemW3h {
    unsigned a[64][36];
    unsigned b[256][36];
};
__global__ __launch_bounds__(256) void k_w3h_mma(const float* __restrict__ W3) {
    constexpr unsigned SB = sizeof(SmemW3h);
    __shared__ __align__(16) char sb[SB];
    SmemW3h& sm = *(SmemW3h*)sb;
    int t = threadIdx.x, warp = t >> 5, lane = t & 31;
    int cg = blockIdx.x & 15;
    int o0 = cg * 256, n0 = (blockIdx.x >> 4) * 64;

    for (int i = t; i < 64 * 8; i += 256) {
        int n = i >> 3, kq = i & 7;
        float4 v = make_float4(0.f, 0.f, 0.f, 0.f);
        if (n0 + n < NN) v = *(const float4*)&g_h[(n0 + n) * 32 + kq * 4];
        sm.a[n][kq * 4 + 0] = f2tf32(v.x); sm.a[n][kq * 4 + 1] = f2tf32(v.y);
        sm.a[n][kq * 4 + 2] = f2tf32(v.z); sm.a[n][kq * 4 + 3] = f2tf32(v.w);
    }
    for (int i = t; i < 256 * 8; i += 256) {
        int o = i >> 3, kq = i & 7;
        float4 v = *(const float4*)&W3[(size_t)(o0 + o) * 32 + kq * 4];
        sm.b[o][kq * 4 + 0] = f2tf32(v.x); sm.b[o][kq * 4 + 1] = f2tf32(v.y);
        sm.b[o][kq * 4 + 2] = f2tf32(v.z); sm.b[o][kq * 4 + 3] = f2tf32(v.w);
    }
    __syncthreads();

    int wm = warp & 3, wn = warp >> 2;
    int qr = lane >> 2, qc = lane & 3;
    float acc[16][4];
#pragma unroll
    for (int nt = 0; nt < 16; nt++)
#pragma unroll
        for (int j = 0; j < 4; j++) acc[nt][j] = 0.f;

#pragma unroll
    for (int ks = 0; ks < 4; ks++) {
        int k0 = ks * 8;
        unsigned a0 = sm.a[wm * 16 + qr][k0 + qc];
        unsigned a1 = sm.a[wm * 16 + qr + 8][k0 + qc];
        unsigned a2 = sm.a[wm * 16 + qr][k0 + qc + 4];
        unsigned a3 = sm.a[wm * 16 + qr + 8][k0 + qc + 4];
#pragma unroll
        for (int nt = 0; nt < 16; nt++) {
            int ob = wn * 128 + nt * 8;
            unsigned b0 = sm.b[ob + qr][k0 + qc];
            unsigned b1 = sm.b[ob + qr][k0 + qc + 4];
            mma_tf32(acc[nt][0], acc[nt][1], acc[nt][2], acc[nt][3],
                     a0, a1, a2, a3, b0, b1);
        }
    }
    __syncthreads();

    unsigned* so = (unsigned*)sb;
    int nlA = wm * 16 + qr, nlB = nlA + 8;
#pragma unroll
    for (int g = 0; g < 8; g++) {
        int ntA = (g & 3) + (g >> 2) * 8;
#pragma unroll
        for (int j = 0; j < 2; j++) {
            int w = (g & 3) * 32 + (2 * qc + j) * 4 + wn * 2 + (g >> 2);
            __half2 vA = __floats2half2_rn(acc[ntA][j], acc[ntA + 4][j]);
            __half2 vB = __floats2half2_rn(acc[ntA][2 + j], acc[ntA + 4][2 + j]);
            so[nlA * 132 + w] = *(unsigned*)&vA;
            so[nlB * 132 + w] = *(unsigned*)&vB;
        }
    }
    __syncthreads();

    int ks = cg >> 1, par = cg & 1;
    for (int r = warp; r < 64; r += 8) {
        int n = n0 + r;
        if (n < NN) {
#pragma unroll
            for (int ch = 0; ch < 4; ch++)
                g_W3hB[(size_t)n * 2048 + ks * 256 + ch * 64 + par * 32 + lane] =
                    so[r * 132 + ch * 32 + lane];
        }
    }
}

// -------- contraction: fp16 mma for m AND phi; staged B3; warp per node ----------
__global__ __launch_bounds__(128) void k_contract_mma(
    const int* __restrict__ ei, const float* __restrict__ B3,
    const float* __restrict__ CW1, const float* __restrict__ CB1,
    const float* __restrict__ CW2) {
    __shared__ float  s_cw1[32][33];   // [j][i]
    __shared__ float  s_b3t[32][33];   // [j][i] = B3[i*32+j]
    __shared__ __half s_a[4][16][136];
    __shared__ float  s_m[4][16][33];
    __shared__ float  s_p[4][16][33];
    __shared__ int    s_e[4][16];
    __shared__ int    s_rn[4][16];
    int t = threadIdx.x, lane = t & 31, w = t >> 5;
    for (int i = t; i < 1024; i += 128) {
        s_cw1[i >> 5][i & 31] = CW1[i];
        s_b3t[i & 31][i >> 5] = B3[i];
    }
    __syncthreads();

    int n = blockIdx.x * 4 + w;
    if (n >= NN) return;
    int beg = g_cptr[n], end = g_cptr[n + 1];
    if (beg == end) return;

    int qr = lane >> 2, qc = lane & 3;

    // W3h B fragments: 64 coalesced 128B lines
    unsigned u[64];
    const unsigned* bp = g_W3hB + (size_t)n * 2048 + lane;
#pragma unroll
    for (int f = 0; f < 64; f++) u[f] = bp[f * 32];

    // CW1 B fragments for phi mma (per warp, constant)
    unsigned ucw[2][4][2];
#pragma unroll
    for (int ks2 = 0; ks2 < 2; ks2++)
#pragma unroll
        for (int nt = 0; nt < 4; nt++) {
            int kb = ks2 * 16 + 2 * qc, nb = nt * 8 + qr;
            ucw[ks2][nt][0] = packh2(s_cw1[kb][nb], s_cw1[kb + 1][nb]);
            ucw[ks2][nt][1] = packh2(s_cw1[kb + 8][nb], s_cw1[kb + 9][nb]);
        }

    // bias terms
    float hv = g_h[n * 32 + lane];
    float bh = 0.f;
#pragma unroll
    for (int j = 0; j < 32; j++)
        bh = fmaf(s_b3t[j][lane], __shfl_sync(0xffffffffu, hv, j), bh);
    float bterm = CB1[lane];
#pragma unroll
    for (int j = 0; j < 32; j++)
        bterm = fmaf(__shfl_sync(0xffffffffu, bh, j), s_cw1[j][lane], bterm);

    float cc = (lane < 3) ? g_coord[n * 3 + lane] : 0.f;
    float cw2l = CW2[lane];

    for (int g0 = beg; g0 < end; g0 += 16) {
        int gsz = min(16, end - g0);
        if (lane < 16) {
            int e = (lane < gsz) ? g_ebc[g0 + lane] : g_ebc[g0];
            s_e[w][lane] = e;
            s_rn[w][lane] = ei[e];
        }
        __syncwarp();
#pragma unroll
        for (int it = 0; it < 8; it++) {
            int idx = it * 32 + lane;
            int row = idx >> 4, part = idx & 15;
            ((uint4*)&s_a[w][row][0])[part] =
                ((const uint4*)(g_k2h + (size_t)s_e[w][row] * 128))[part];
        }
        __syncwarp();

        float acc[4][4];
#pragma unroll
        for (int nt = 0; nt < 4; nt++)
#pragma unroll
            for (int j = 0; j < 4; j++) acc[nt][j] = 0.f;

#pragma unroll
        for (int ks = 0; ks < 8; ks++) {
            int k0 = ks * 16 + 2 * qc;
            unsigned a0 = *(const unsigned*)&s_a[w][qr][k0];
            unsigned a1 = *(const unsigned*)&s_a[w][qr + 8][k0];
            unsigned a2 = *(const unsigned*)&s_a[w][qr][k0 + 8];
            unsigned a3 = *(const unsigned*)&s_a[w][qr + 8][k0 + 8];
#pragma unroll
            for (int nt = 0; nt < 4; nt++)
                mma_f16(acc[nt][0], acc[nt][1], acc[nt][2], acc[nt][3],
                        a0, a1, a2, a3, u[(ks * 4 + nt) * 2], u[(ks * 4 + nt) * 2 + 1]);
        }
        __syncwarp();
#pragma unroll
        for (int nt = 0; nt < 4; nt++) {
#pragma unroll
            for (int j = 0; j < 2; j++) {
                s_m[w][qr][nt * 8 + 2 * qc + j] = acc[nt][j];
                s_m[w][qr + 8][nt * 8 + 2 * qc + j] = acc[nt][2 + j];
            }
        }
        __syncwarp();

        // phi mma: phi_pre[16,32] = M[16,32] @ CW1[32,32]
        float pacc[4][4];
#pragma unroll
        for (int nt = 0; nt < 4; nt++)
#pragma unroll
            for (int j = 0; j < 4; j++) pacc[nt][j] = 0.f;
#pragma unroll
        for (int ks2 = 0; ks2 < 2; ks2++) {
            int kb = ks2 * 16 + 2 * qc;
            unsigned a0 = packh2(s_m[w][qr][kb], s_m[w][qr][kb + 1]);
            unsigned a1 = packh2(s_m[w][qr + 8][kb], s_m[w][qr + 8][kb + 1]);
            unsigned a2 = packh2(s_m[w][qr][kb + 8], s_m[w][qr][kb + 9]);
            unsigned a3 = packh2(s_m[w][qr + 8][kb + 8], s_m[w][qr + 8][kb + 9]);
#pragma unroll
            for (int nt = 0; nt < 4; nt++)
                mma_f16(pacc[nt][0], pacc[nt][1], pacc[nt][2], pacc[nt][3],
                        a0, a1, a2, a3, ucw[ks2][nt][0], ucw[ks2][nt][1]);
        }
#pragma unroll
        for (int nt = 0; nt < 4; nt++) {
#pragma unroll
            for (int j = 0; j < 2; j++) {
                s_p[w][qr][nt * 8 + 2 * qc + j] = pacc[nt][j];
                s_p[w][qr + 8][nt * 8 + 2 * qc + j] = pacc[nt][2 + j];
            }
        }
        __syncwarp();

        for (int r = 0; r < gsz; r++) {
            int rn = s_rn[w][r];
            float mi = s_m[w][r][lane] + bh;
            float tj = fmaxf(s_p[w][r][lane] + bterm, 0.f) * cw2l;
#pragma unroll
            for (int o = 16; o; o >>= 1) tj += __shfl_xor_sync(0xffffffffu, tj, o);

            atomicAdd(&g_acch[rn * 32 + lane], mi);
            if (lane < 3)
                atomicAdd(&g_accc[rn * 3 + lane], (g_coord[rn * 3 + lane] - cc) * tj);
        }
        __syncwarp();
    }
}

// ---------------- node update (invc inlined) --------------------------------------
__global__ void k_update() {
    int idx = blockIdx.x * blockDim.x + threadIdx.x;
    if (idx >= NN * 32) return;
    int n = idx >> 5, j = idx & 31;
    int c = g_cntr[n];
    float inv = 1.f / (float)(c > 0 ? c : 1);
    g_h[idx] = fmaxf(g_h[idx] + g_acch[idx] * inv, 0.f);
    g_acch[idx] = 0.f;
    if (j < 3) {
        g_coord[n * 3 + j] += g_accc[n * 3 + j] * inv;
        g_accc[n * 3 + j] = 0.f;
    }
}

// ---------------- final MLP + coord copy ------------------------------------------
__global__ void k_final(const float* __restrict__ w1, const float* __restrict__ b1,
                        const float* __restrict__ w2, const float* __restrict__ b2,
                        float* __restrict__ out) {
    int gid = blockIdx.x * blockDim.x + threadIdx.x;
    if (gid < NN * 3) out[NN + gid] = g_coord[gid];
    int lane = gid & 31;
    int n = gid >> 5;
    if (n >= NN) return;
    float hv = g_h[n * 32 + lane];
    float t0 = b1[lane], t1 = b1[32 + lane];
#pragma unroll
    for (int j = 0; j < 32; j++) {
        float hj = __shfl_sync(0xffffffffu, hv, j);
        t0 = fmaf(hj, w1[j * 64 + lane], t0);
        t1 = fmaf(hj, w1[j * 64 + 32 + lane], t1);
    }
    float s = fmaxf(t0, 0.f) * w2[lane] + fmaxf(t1, 0.f) * w2[32 + lane];
#pragma unroll
    for (int o = 16; o; o >>= 1) s += __shfl_xor_sync(0xffffffffu, s, o);
    if (lane == 0) out[n] = s + b2[0];
}

// ---------------------------------------------------------------------------------
extern "C" void kernel_launch(void* const* d_in, const int* in_sizes, int n_in,
                              void* d_out, int out_size) {
    const float* x    = (const float*)d_in[0];
    const int*   ei   = (const int*)d_in[1];
    const float* attr = (const float*)d_in[2];
    const float* ci   = (const float*)d_in[3];
    const float* f1w  = (const float*)d_in[4];
    const float* f1b  = (const float*)d_in[5];
    const float* kw1  = (const float*)d_in[6];
    const float* kb1  = (const float*)d_in[7];
    const float* kw2  = (const float*)d_in[8];
    const float* kb2  = (const float*)d_in[9];
    const float* kw3  = (const float*)d_in[10];
    const float* kb3  = (const float*)d_in[11];
    const float* cw1  = (const float*)d_in[12];
    const float* cb1  = (const float*)d_in[13];
    const float* cw2  = (const float*)d_in[14];
    const float* f2w1 = (const float*)d_in[15];
    const float* f2b1 = (const float*)d_in[16];
    const float* f2w2 = (const float*)d_in[17];
    const float* f2b2 = (const float*)d_in[18];
    float* out = (float*)d_out;

    int w3h_grid = ((NN + 63) / 64) * 16;
    int edge_grid = (EE + 63) / 64;

    k_prep<<<(NN * 32 + 255) / 256, 256>>>(x, f1w, f1b, ci);            // 0
    k_hist<<<(EE + 255) / 256, 256>>>(ei);                               // 1
    k_scan<<<1, 1024>>>();                                               // 2
    k_edge_mma<<<edge_grid, 256>>>(ei, attr, kw1, kb1, kw2, kb2);        // 3 <- profiled
    k_scatter<<<(EE + 255) / 256, 256>>>(ei);                            // 4
    k_w3h_mma<<<w3h_grid, 256>>>(kw3);                                   // 5 (L0)
    k_contract_mma<<<(NN + 3) / 4, 128>>>(ei, kb3, cw1, cb1, cw2);       // 6 (L0)
    k_update<<<(NN * 32 + 255) / 256, 256>>>();                          // 7 (L0)

    for (int L = 1; L < 3; L++) {
        k_edge_mma<<<edge_grid, 256>>>(ei, attr, kw1, kb1, kw2, kb2);
        k_w3h_mma<<<w3h_grid, 256>>>(kw3);
        k_contract_mma<<<(NN + 3) / 4, 128>>>(ei, kb3, cw1, cb1, cw2);
        k_update<<<(NN * 32 + 255) / 256, 256>>>();
    }

    k_final<<<(NN * 32 + 255) / 256, 256>>>(f2w1, f2b1, f2w2, f2b2, out);
}

// round 10
// speedup vs baseline: 2.1645x; 1.0962x over previous
#include <cuda_runtime.h>
#include <cuda_fp16.h>

#define NN 10000
#define EE 100000

// ---------------- scratch (static device globals; no allocation) ----------------
__device__ float g_h[NN * 32];
__device__ float g_coord[NN * 3];
__device__ __align__(16) __half g_k2h[(size_t)EE * 128];
__device__ unsigned g_W3hB[(size_t)NN * 2048];   // [n][frag:64][lane:32] half2 words
__device__ float g_acch[NN * 32];
__device__ float g_accc[NN * 3];
__device__ int   g_cntc[NN];
__device__ int   g_cntr[NN];
__device__ int   g_fill[NN];
__device__ int   g_cptr[NN + 1];
__device__ int   g_ebc[EE];

__device__ __forceinline__ unsigned f2tf32(float f) {
    unsigned u;
    asm("cvt.rna.tf32.f32 %0, %1;" : "=r"(u) : "f"(f));
    return u;
}
__device__ __forceinline__ void mma_tf32(float& c0, float& c1, float& c2, float& c3,
                                         unsigned a0, unsigned a1, unsigned a2, unsigned a3,
                                         unsigned b0, unsigned b1) {
    asm("mma.sync.aligned.m16n8k8.row.col.f32.tf32.tf32.f32 "
        "{%0,%1,%2,%3}, {%4,%5,%6,%7}, {%8,%9}, {%0,%1,%2,%3};"
        : "+f"(c0), "+f"(c1), "+f"(c2), "+f"(c3)
        : "r"(a0), "r"(a1), "r"(a2), "r"(a3), "r"(b0), "r"(b1));
}
__device__ __forceinline__ void mma_f16(float& c0, float& c1, float& c2, float& c3,
                                        unsigned a0, unsigned a1, unsigned a2, unsigned a3,
                                        unsigned b0, unsigned b1) {
    asm("mma.sync.aligned.m16n8k16.row.col.f32.f16.f16.f32 "
        "{%0,%1,%2,%3}, {%4,%5,%6,%7}, {%8,%9}, {%0,%1,%2,%3};"
        : "+f"(c0), "+f"(c1), "+f"(c2), "+f"(c3)
        : "r"(a0), "r"(a1), "r"(a2), "r"(a3), "r"(b0), "r"(b1));
}
__device__ __forceinline__ unsigned packh2(float a, float b) {
    __half2 h = __floats2half2_rn(a, b);
    return *(unsigned*)&h;
}

// ---------------- init ----------------
__global__ void k_prep(const float* __restrict__ x, const float* __restrict__ w,
                       const float* __restrict__ b, const float* __restrict__ ci) {
    int idx = blockIdx.x * blockDim.x + threadIdx.x;
    if (idx < NN * 32) {
        int n = idx >> 5, j = idx & 31;
        float s = b[j];
        s += x[n * 3 + 0] * w[j] + x[n * 3 + 1] * w[32 + j] + x[n * 3 + 2] * w[64 + j];
        g_h[idx] = s;
        g_acch[idx] = 0.f;
    }
    if (idx < NN * 3) { g_coord[idx] = ci[idx]; g_accc[idx] = 0.f; }
    if (idx < NN) { g_cntc[idx] = 0; g_cntr[idx] = 0; g_fill[idx] = 0; }
}

__global__ void k_hist(const int* __restrict__ ei) {
    int e = blockIdx.x * blockDim.x + threadIdx.x;
    if (e < EE) {
        atomicAdd(&g_cntr[ei[e]], 1);
        atomicAdd(&g_cntc[ei[EE + e]], 1);
    }
}

__global__ void k_scan() {
    __shared__ int ss[1024];
    int t = threadIdx.x;
    int base = t * 10;
    int loc[10];
    int s = 0;
#pragma unroll
    for (int i = 0; i < 10; i++) {
        int v = (base + i < NN) ? g_cntc[base + i] : 0;
        loc[i] = s; s += v;
    }
    ss[t] = s;
    __syncthreads();
    for (int off = 1; off < 1024; off <<= 1) {
        int v = (t >= off) ? ss[t - off] : 0;
        __syncthreads();
        ss[t] += v;
        __syncthreads();
    }
    int pre = (t > 0) ? ss[t - 1] : 0;
#pragma unroll
    for (int i = 0; i < 10; i++)
        if (base + i < NN) g_cptr[base + i] = pre + loc[i];
    if (t == 1023) g_cptr[NN] = ss[1023];
}

__global__ void k_scatter(const int* __restrict__ ei) {
    int e = blockIdx.x * blockDim.x + threadIdx.x;
    if (e < EE) {
        int c = ei[EE + e];
        int p = g_cptr[c] + atomicAdd(&g_fill[c], 1);
        g_ebc[p] = e;
    }
}

// -------- edge MLP: k1 scalar, k2 via single tf32 mma, fp16 output ----------------
__global__ __launch_bounds__(256) void k_edge_mma(
    const int* __restrict__ ei, const float* __restrict__ attr,
    const float* __restrict__ W1, const float* __restrict__ B1,
    const float* __restrict__ W2, const float* __restrict__ B2) {
    __shared__ unsigned s_w2t[128][36];   // [col][kk] tf32
    __shared__ unsigned s_k1[64][36];     // [edge][kk] tf32
    __shared__ float s_kin[64][8];
    __shared__ float s_w1[7 * 64];
    __shared__ float s_b1[64];
    __shared__ float s_b2[128];
    int t = threadIdx.x, warp = t >> 5, lane = t & 31;
    int e0 = blockIdx.x * 64;

    for (int i = t; i < 7 * 64; i += 256) s_w1[i] = W1[i];
    if (t < 64) s_b1[t] = B1[t];
    else if (t < 192) s_b2[t - 64] = B2[t - 64];

    if (t < 64) {
        int e = e0 + t;
        float rad = 0.f;
        if (e < EE) {
            int r = ei[e], c = ei[EE + e];
            float d0 = g_coord[r * 3 + 0] - g_coord[c * 3 + 0];
            float d1 = g_coord[r * 3 + 1] - g_coord[c * 3 + 1];
            float d2 = g_coord[r * 3 + 2] - g_coord[c * 3 + 2];
            rad = d0 * d0 + d1 * d1 + d2 * d2;
#pragma unroll
            for (int q = 0; q < 6; q++) s_kin[t][q] = attr[e * 6 + q];
        } else {
#pragma unroll
            for (int q = 0; q < 6; q++) s_kin[t][q] = 0.f;
        }
        s_kin[t][6] = rad;
        s_kin[t][7] = 0.f;
    }
    __syncthreads();

    int wm = warp & 3, wn = warp >> 2;
    int qr = lane >> 2, qc = lane & 3;
    float acc[8][4];
#pragma unroll
    for (int nt = 0; nt < 8; nt++)
#pragma unroll
        for (int j = 0; j < 4; j++) acc[nt][j] = 0.f;

    for (int half = 0; half < 2; half++) {
        for (int i = t; i < 128 * 32; i += 256) {
            int col = i & 127, kk = i >> 7;
            s_w2t[col][kk] = f2tf32(W2[(half * 32 + kk) * 128 + col]);
        }
        for (int i = t; i < 64 * 32; i += 256) {
            int e = i >> 5, cc = i & 31, c = half * 32 + cc;
            float s = s_b1[c];
#pragma unroll
            for (int q = 0; q < 7; q++) s = fmaf(s_kin[e][q], s_w1[q * 64 + c], s);
            s_k1[e][cc] = f2tf32(fmaxf(s, 0.f));
        }
        __syncthreads();

#pragma unroll
        for (int ks = 0; ks < 4; ks++) {
            int k0 = ks * 8;
            unsigned a0 = s_k1[wm * 16 + qr][k0 + qc];
            unsigned a1 = s_k1[wm * 16 + qr + 8][k0 + qc];
            unsigned a2 = s_k1[wm * 16 + qr][k0 + qc + 4];
            unsigned a3 = s_k1[wm * 16 + qr + 8][k0 + qc + 4];
#pragma unroll
            for (int nt = 0; nt < 8; nt++) {
                int col = wn * 64 + nt * 8;
                unsigned b0 = s_w2t[col + qr][k0 + qc];
                unsigned b1 = s_w2t[col + qr][k0 + qc + 4];
                mma_tf32(acc[nt][0], acc[nt][1], acc[nt][2], acc[nt][3],
                         a0, a1, a2, a3, b0, b1);
            }
        }
        __syncthreads();
    }

    int eA = e0 + wm * 16 + qr, eB = eA + 8;
#pragma unroll
    for (int nt = 0; nt < 8; nt++) {
        int col = wn * 64 + nt * 8 + 2 * qc;
        float bx = s_b2[col], by = s_b2[col + 1];
        if (eA < EE)
            *(__half2*)&g_k2h[(size_t)eA * 128 + col] =
                __floats2half2_rn(fmaxf(acc[nt][0] + bx, 0.f), fmaxf(acc[nt][1] + by, 0.f));
        if (eB < EE)
            *(__half2*)&g_k2h[(size_t)eB * 128 + col] =
                __floats2half2_rn(fmaxf(acc[nt][2] + bx, 0.f), fmaxf(acc[nt][3] + by, 0.f));
    }
}

// -------- W3h via tf32 mma, retiled 32n x 256o (2 m-warps x 4 n-warps) ------------
// Higher occupancy: acc[8][4]=32 regs/thread. Same B-fragment output layout.
struct SmemW3h {
    unsigned a[32][36];
    unsigned b[256][36];
};
__global__ __launch_bounds__(256) void k_w3h_mma(const float* __restrict__ W3) {
    __shared__ __align__(16) char sb[sizeof(SmemW3h)];   // 41472 B; epilogue needs 16896
    SmemW3h& sm = *(SmemW3h*)sb;
    int t = threadIdx.x, warp = t >> 5, lane = t & 31;
    int cg = blockIdx.x & 15;
    int o0 = cg * 256, n0 = (blockIdx.x >> 4) * 32;

    // stage A: 32 x 32, one float4 per thread
    {
        int n = t >> 3, kq = t & 7;
        float4 v = make_float4(0.f, 0.f, 0.f, 0.f);
        if (n0 + n < NN) v = *(const float4*)&g_h[(n0 + n) * 32 + kq * 4];
        sm.a[n][kq * 4 + 0] = f2tf32(v.x); sm.a[n][kq * 4 + 1] = f2tf32(v.y);
        sm.a[n][kq * 4 + 2] = f2tf32(v.z); sm.a[n][kq * 4 + 3] = f2tf32(v.w);
    }
    // stage B: 256 x 32
    for (int i = t; i < 256 * 8; i += 256) {
        int o = i >> 3, kq = i & 7;
        float4 v = *(const float4*)&W3[(size_t)(o0 + o) * 32 + kq * 4];
        sm.b[o][kq * 4 + 0] = f2tf32(v.x); sm.b[o][kq * 4 + 1] = f2tf32(v.y);
        sm.b[o][kq * 4 + 2] = f2tf32(v.z); sm.b[o][kq * 4 + 3] = f2tf32(v.w);
    }
    __syncthreads();

    int wm = warp & 1, wn = warp >> 1;   // wm: 16-row group; wn: 64-out group
    int qr = lane >> 2, qc = lane & 3;
    float acc[8][4];
#pragma unroll
    for (int nt = 0; nt < 8; nt++)
#pragma unroll
        for (int j = 0; j < 4; j++) acc[nt][j] = 0.f;

#pragma unroll
    for (int ks = 0; ks < 4; ks++) {
        int k0 = ks * 8;
        unsigned a0 = sm.a[wm * 16 + qr][k0 + qc];
        unsigned a1 = sm.a[wm * 16 + qr + 8][k0 + qc];
        unsigned a2 = sm.a[wm * 16 + qr][k0 + qc + 4];
        unsigned a3 = sm.a[wm * 16 + qr + 8][k0 + qc + 4];
#pragma unroll
        for (int nt = 0; nt < 8; nt++) {
            int ob = wn * 64 + nt * 8;
            unsigned b0 = sm.b[ob + qr][k0 + qc];
            unsigned b1 = sm.b[ob + qr][k0 + qc + 4];
            mma_tf32(acc[nt][0], acc[nt][1], acc[nt][2], acc[nt][3],
                     a0, a1, a2, a3, b0, b1);
        }
    }
    __syncthreads();   // staging dead; reuse as half2 tile (32 rows x 132 words)

    // pair (nt, nt+4): same i, c_local pair (wn*2, wn*2+1) -> l&3 = wn
    unsigned* so = (unsigned*)sb;
    int nlA = wm * 16 + qr, nlB = nlA + 8;
#pragma unroll
    for (int g = 0; g < 4; g++) {
#pragma unroll
        for (int j = 0; j < 2; j++) {
            int w = g * 32 + (2 * qc + j) * 4 + wn;
            __half2 vA = __floats2half2_rn(acc[g][j], acc[g + 4][j]);
            __half2 vB = __floats2half2_rn(acc[g][2 + j], acc[g + 4][2 + j]);
            so[nlA * 132 + w] = *(unsigned*)&vA;
            so[nlB * 132 + w] = *(unsigned*)&vB;
        }
    }
    __syncthreads();

    int ks = cg >> 1, par = cg & 1;
    for (int r = warp; r < 32; r += 8) {
        int n = n0 + r;
        if (n < NN) {
#pragma unroll
            for (int ch = 0; ch < 4; ch++)
                g_W3hB[(size_t)n * 2048 + ks * 256 + ch * 64 + par * 32 + lane] =
                    so[r * 132 + ch * 32 + lane];
        }
    }
}

// -------- contraction: fp16 mma for m AND phi; lane-parallel epilogue -------------
__global__ __launch_bounds__(128) void k_contract_mma(
    const int* __restrict__ ei, const float* __restrict__ B3,
    const float* __restrict__ CW1, const float* __restrict__ CB1,
    const float* __restrict__ CW2) {
    __shared__ float  s_cw1[32][33];   // [j][i]
    __shared__ float  s_b3t[32][33];   // [j][i] = B3[i*32+j]
    __shared__ float  s_cw2[32];
    __shared__ __half s_a[4][16][136];
    __shared__ float  s_m[4][16][33];
    __shared__ float  s_p[4][16][33];
    __shared__ float  s_bt[4][32];
    __shared__ float  s_cc[4][4];
    __shared__ int    s_e[4][16];
    __shared__ int    s_rn[4][16];
    int t = threadIdx.x, lane = t & 31, w = t >> 5;
    for (int i = t; i < 1024; i += 128) {
        s_cw1[i >> 5][i & 31] = CW1[i];
        s_b3t[i & 31][i >> 5] = B3[i];
    }
    if (t < 32) s_cw2[t] = CW2[t];
    __syncthreads();

    int n = blockIdx.x * 4 + w;
    if (n >= NN) return;
    int beg = g_cptr[n], end = g_cptr[n + 1];
    if (beg == end) return;

    int qr = lane >> 2, qc = lane & 3;

    // W3h B fragments: 64 coalesced 128B lines
    unsigned u[64];
    const unsigned* bp = g_W3hB + (size_t)n * 2048 + lane;
#pragma unroll
    for (int f = 0; f < 64; f++) u[f] = bp[f * 32];

    // CW1 B fragments for phi mma
    unsigned ucw[2][4][2];
#pragma unroll
    for (int ks2 = 0; ks2 < 2; ks2++)
#pragma unroll
        for (int nt = 0; nt < 4; nt++) {
            int kb = ks2 * 16 + 2 * qc, nb = nt * 8 + qr;
            ucw[ks2][nt][0] = packh2(s_cw1[kb][nb], s_cw1[kb + 1][nb]);
            ucw[ks2][nt][1] = packh2(s_cw1[kb + 8][nb], s_cw1[kb + 9][nb]);
        }

    // per-node bias terms
    float hv = g_h[n * 32 + lane];
    float bh = 0.f;
#pragma unroll
    for (int j = 0; j < 32; j++)
        bh = fmaf(s_b3t[j][lane], __shfl_sync(0xffffffffu, hv, j), bh);
    float bterm = CB1[lane];
#pragma unroll
    for (int j = 0; j < 32; j++)
        bterm = fmaf(__shfl_sync(0xffffffffu, bh, j), s_cw1[j][lane], bterm);
    s_bt[w][lane] = bterm;
    if (lane < 3) s_cc[w][lane] = g_coord[n * 3 + lane];
    __syncwarp();

    for (int g0 = beg; g0 < end; g0 += 16) {
        int gsz = min(16, end - g0);
        if (lane < 16) {
            int e = (lane < gsz) ? g_ebc[g0 + lane] : g_ebc[g0];
            s_e[w][lane] = e;
            s_rn[w][lane] = ei[e];
        }
        __syncwarp();
#pragma unroll
        for (int it = 0; it < 8; it++) {
            int idx = it * 32 + lane;
            int row = idx >> 4, part = idx & 15;
            ((uint4*)&s_a[w][row][0])[part] =
                ((const uint4*)(g_k2h + (size_t)s_e[w][row] * 128))[part];
        }
        __syncwarp();

        float acc[4][4];
#pragma unroll
        for (int nt = 0; nt < 4; nt++)
#pragma unroll
            for (int j = 0; j < 4; j++) acc[nt][j] = 0.f;

#pragma unroll
        for (int ks = 0; ks < 8; ks++) {
            int k0 = ks * 16 + 2 * qc;
            unsigned a0 = *(const unsigned*)&s_a[w][qr][k0];
            unsigned a1 = *(const unsigned*)&s_a[w][qr + 8][k0];
            unsigned a2 = *(const unsigned*)&s_a[w][qr][k0 + 8];
            unsigned a3 = *(const unsigned*)&s_a[w][qr + 8][k0 + 8];
#pragma unroll
            for (int nt = 0; nt < 4; nt++)
                mma_f16(acc[nt][0], acc[nt][1], acc[nt][2], acc[nt][3],
                        a0, a1, a2, a3, u[(ks * 4 + nt) * 2], u[(ks * 4 + nt) * 2 + 1]);
        }
        __syncwarp();
#pragma unroll
        for (int nt = 0; nt < 4; nt++) {
#pragma unroll
            for (int j = 0; j < 2; j++) {
                s_m[w][qr][nt * 8 + 2 * qc + j] = acc[nt][j];
                s_m[w][qr + 8][nt * 8 + 2 * qc + j] = acc[nt][2 + j];
            }
        }
        __syncwarp();

        // phi mma: phi_pre[16,32] = M[16,32] @ CW1[32,32]
        float pacc[4][4];
#pragma unroll
        for (int nt = 0; nt < 4; nt++)
#pragma unroll
            for (int j = 0; j < 4; j++) pacc[nt][j] = 0.f;
#pragma unroll
        for (int ks2 = 0; ks2 < 2; ks2++) {
            int kb = ks2 * 16 + 2 * qc;
            unsigned a0 = packh2(s_m[w][qr][kb], s_m[w][qr][kb + 1]);
            unsigned a1 = packh2(s_m[w][qr + 8][kb], s_m[w][qr + 8][kb + 1]);
            unsigned a2 = packh2(s_m[w][qr][kb + 8], s_m[w][qr][kb + 9]);
            unsigned a3 = packh2(s_m[w][qr + 8][kb + 8], s_m[w][qr + 8][kb + 9]);
#pragma unroll
            for (int nt = 0; nt < 4; nt++)
                mma_f16(pacc[nt][0], pacc[nt][1], pacc[nt][2], pacc[nt][3],
                        a0, a1, a2, a3, ucw[ks2][nt][0], ucw[ks2][nt][1]);
        }
#pragma unroll
        for (int nt = 0; nt < 4; nt++) {
#pragma unroll
            for (int j = 0; j < 2; j++) {
                s_p[w][qr][nt * 8 + 2 * qc + j] = pacc[nt][j];
                s_p[w][qr + 8][nt * 8 + 2 * qc + j] = pacc[nt][2 + j];
            }
        }
        __syncwarp();

        // lane-parallel tj: lane r handles edge r (conflict-free: bank = r + i)
        int rr = lane & 15;
        float tj = 0.f;
#pragma unroll
        for (int i = 0; i < 32; i++)
            tj = fmaf(fmaxf(s_p[w][rr][i] + s_bt[w][i], 0.f), s_cw2[i], tj);
        if (lane < gsz) {
            int rn = s_rn[w][lane];
#pragma unroll
            for (int k = 0; k < 3; k++)
                atomicAdd(&g_accc[rn * 3 + k],
                          (g_coord[rn * 3 + k] - s_cc[w][k]) * tj);
        }

        for (int r = 0; r < gsz; r++) {
            int rn = s_rn[w][r];
            float mi = s_m[w][r][lane] + bh;
            atomicAdd(&g_acch[rn * 32 + lane], mi);
        }
        __syncwarp();
    }
}

// ---------------- node update (invc inlined) --------------------------------------
__global__ void k_update() {
    int idx = blockIdx.x * blockDim.x + threadIdx.x;
    if (idx >= NN * 32) return;
    int n = idx >> 5, j = idx & 31;
    int c = g_cntr[n];
    float inv = 1.f / (float)(c > 0 ? c : 1);
    g_h[idx] = fmaxf(g_h[idx] + g_acch[idx] * inv, 0.f);
    g_acch[idx] = 0.f;
    if (j < 3) {
        g_coord[n * 3 + j] += g_accc[n * 3 + j] * inv;
        g_accc[n * 3 + j] = 0.f;
    }
}

// ---------------- final MLP + coord copy ------------------------------------------
__global__ void k_final(const float* __restrict__ w1, const float* __restrict__ b1,
                        const float* __restrict__ w2, const float* __restrict__ b2,
                        float* __restrict__ out) {
    int gid = blockIdx.x * blockDim.x + threadIdx.x;
    if (gid < NN * 3) out[NN + gid] = g_coord[gid];
    int lane = gid & 31;
    int n = gid >> 5;
    if (n >= NN) return;
    float hv = g_h[n * 32 + lane];
    float t0 = b1[lane], t1 = b1[32 + lane];
#pragma unroll
    for (int j = 0; j < 32; j++) {
        float hj = __shfl_sync(0xffffffffu, hv, j);
        t0 = fmaf(hj, w1[j * 64 + lane], t0);
        t1 = fmaf(hj, w1[j * 64 + 32 + lane], t1);
    }
    float s = fmaxf(t0, 0.f) * w2[lane] + fmaxf(t1, 0.f) * w2[32 + lane];
#pragma unroll
    for (int o = 16; o; o >>= 1) s += __shfl_xor_sync(0xffffffffu, s, o);
    if (lane == 0) out[n] = s + b2[0];
}

// ---------------------------------------------------------------------------------
extern "C" void kernel_launch(void* const* d_in, const int* in_sizes, int n_in,
                              void* d_out, int out_size) {
    const float* x    = (const float*)d_in[0];
    const int*   ei   = (const int*)d_in[1];
    const float* attr = (const float*)d_in[2];
    const float* ci   = (const float*)d_in[3];
    const float* f1w  = (const float*)d_in[4];
    const float* f1b  = (const float*)d_in[5];
    const float* kw1  = (const float*)d_in[6];
    const float* kb1  = (const float*)d_in[7];
    const float* kw2  = (const float*)d_in[8];
    const float* kb2  = (const float*)d_in[9];
    const float* kw3  = (const float*)d_in[10];
    const float* kb3  = (const float*)d_in[11];
    const float* cw1  = (const float*)d_in[12];
    const float* cb1  = (const float*)d_in[13];
    const float* cw2  = (const float*)d_in[14];
    const float* f2w1 = (const float*)d_in[15];
    const float* f2b1 = (const float*)d_in[16];
    const float* f2w2 = (const float*)d_in[17];
    const float* f2b2 = (const float*)d_in[18];
    float* out = (float*)d_out;

    int w3h_grid = ((NN + 31) / 32) * 16;
    int edge_grid = (EE + 63) / 64;

    k_prep<<<(NN * 32 + 255) / 256, 256>>>(x, f1w, f1b, ci);            // 0
    k_hist<<<(EE + 255) / 256, 256>>>(ei);                               // 1
    k_scan<<<1, 1024>>>();                                               // 2
    k_w3h_mma<<<w3h_grid, 256>>>(kw3);                                   // 3 <- profiled
    k_scatter<<<(EE + 255) / 256, 256>>>(ei);                            // 4
    k_edge_mma<<<edge_grid, 256>>>(ei, attr, kw1, kb1, kw2, kb2);        // 5 (L0)
    k_contract_mma<<<(NN + 3) / 4, 128>>>(ei, kb3, cw1, cb1, cw2);       // 6 (L0)
    k_update<<<(NN * 32 + 255) / 256, 256>>>();                          // 7 (L0)

    for (int L = 1; L < 3; L++) {
        k_edge_mma<<<edge_grid, 256>>>(ei, attr, kw1, kb1, kw2, kb2);
        k_w3h_mma<<<w3h_grid, 256>>>(kw3);
        k_contract_mma<<<(NN + 3) / 4, 128>>>(ei, kb3, cw1, cb1, cw2);
        k_update<<<(NN * 32 + 255) / 256, 256>>>();
    }

    k_final<<<(NN * 32 + 255) / 256, 256>>>(f2w1, f2b1, f2w2, f2b2, out);
}

// round 11
// speedup vs baseline: 2.3767x; 1.0980x over previous
#include <cuda_runtime.h>
#include <cuda_fp16.h>

#define NN 10000
#define EE 100000

// ---------------- scratch (static device globals; no allocation) ----------------
__device__ float g_h[NN * 32];
__device__ float g_coord[NN * 3];
__device__ __align__(16) __half g_k2h[(size_t)EE * 128];
__device__ unsigned g_W3hB[(size_t)NN * 2048];   // [n][frag:64][lane:32] half2 words
__device__ __align__(8) unsigned g_W3f[131072];  // prepacked tf32 B-frags of kw3
__device__ __align__(8) unsigned g_W2f[8192];    // prepacked tf32 B-frags of kw2
__device__ float g_acch[NN * 32];
__device__ float g_accc[NN * 3];
__device__ int   g_cntc[NN];
__device__ int   g_cntr[NN];
__device__ int   g_fill[NN];
__device__ int   g_cptr[NN + 1];
__device__ int   g_ebc[EE];

__device__ __forceinline__ unsigned f2tf32(float f) {
    unsigned u;
    asm("cvt.rna.tf32.f32 %0, %1;" : "=r"(u) : "f"(f));
    return u;
}
__device__ __forceinline__ void mma_tf32(float& c0, float& c1, float& c2, float& c3,
                                         unsigned a0, unsigned a1, unsigned a2, unsigned a3,
                                         unsigned b0, unsigned b1) {
    asm("mma.sync.aligned.m16n8k8.row.col.f32.tf32.tf32.f32 "
        "{%0,%1,%2,%3}, {%4,%5,%6,%7}, {%8,%9}, {%0,%1,%2,%3};"
        : "+f"(c0), "+f"(c1), "+f"(c2), "+f"(c3)
        : "r"(a0), "r"(a1), "r"(a2), "r"(a3), "r"(b0), "r"(b1));
}
__device__ __forceinline__ void mma_f16(float& c0, float& c1, float& c2, float& c3,
                                        unsigned a0, unsigned a1, unsigned a2, unsigned a3,
                                        unsigned b0, unsigned b1) {
    asm("mma.sync.aligned.m16n8k16.row.col.f32.f16.f16.f32 "
        "{%0,%1,%2,%3}, {%4,%5,%6,%7}, {%8,%9}, {%0,%1,%2,%3};"
        : "+f"(c0), "+f"(c1), "+f"(c2), "+f"(c3)
        : "r"(a0), "r"(a1), "r"(a2), "r"(a3), "r"(b0), "r"(b1));
}
__device__ __forceinline__ unsigned packh2(float a, float b) {
    __half2 h = __floats2half2_rn(a, b);
    return *(unsigned*)&h;
}

// ---------------- prepack W3/W2 tf32 B-fragments (once per launch) ----------------
// g_W3f word idx = ((cg*32+fo)*4+ks)*64 + lane*2 + b01
//   value = tf32(W3[(cg*256 + fo*8 + qr)*32 + ks*8 + qc + b01*4])
// g_W2f word idx = ((half*16+fo)*4+ks)*64 + lane*2 + b01
//   value = tf32(W2[(half*32 + ks*8 + qc + b01*4)*128 + fo*8 + qr])
__global__ void k_pack(const float* __restrict__ W3, const float* __restrict__ W2) {
    int tid = blockIdx.x * 256 + threadIdx.x;
    if (tid < 131072) {
        int b01 = tid & 1, lane = (tid >> 1) & 31, ks = (tid >> 6) & 3;
        int fo = (tid >> 8) & 31, cg = tid >> 13;
        int qr = lane >> 2, qc = lane & 3;
        g_W3f[tid] = f2tf32(W3[(size_t)(cg * 256 + fo * 8 + qr) * 32 + ks * 8 + qc + b01 * 4]);
    }
    if (tid < 8192) {
        int b01 = tid & 1, lane = (tid >> 1) & 31, ks = (tid >> 6) & 3;
        int fo = (tid >> 8) & 15, half = tid >> 12;
        int qr = lane >> 2, qc = lane & 3;
        g_W2f[tid] = f2tf32(W2[(half * 32 + ks * 8 + qc + b01 * 4) * 128 + fo * 8 + qr]);
    }
}

// ---------------- init ----------------
__global__ void k_prep(const float* __restrict__ x, const float* __restrict__ w,
                       const float* __restrict__ b, const float* __restrict__ ci) {
    int idx = blockIdx.x * blockDim.x + threadIdx.x;
    if (idx < NN * 32) {
        int n = idx >> 5, j = idx & 31;
        float s = b[j];
        s += x[n * 3 + 0] * w[j] + x[n * 3 + 1] * w[32 + j] + x[n * 3 + 2] * w[64 + j];
        g_h[idx] = s;
        g_acch[idx] = 0.f;
    }
    if (idx < NN * 3) { g_coord[idx] = ci[idx]; g_accc[idx] = 0.f; }
    if (idx < NN) { g_cntc[idx] = 0; g_cntr[idx] = 0; g_fill[idx] = 0; }
}

__global__ void k_hist(const int* __restrict__ ei) {
    int e = blockIdx.x * blockDim.x + threadIdx.x;
    if (e < EE) {
        atomicAdd(&g_cntr[ei[e]], 1);
        atomicAdd(&g_cntc[ei[EE + e]], 1);
    }
}

__global__ void k_scan() {
    __shared__ int ss[1024];
    int t = threadIdx.x;
    int base = t * 10;
    int loc[10];
    int s = 0;
#pragma unroll
    for (int i = 0; i < 10; i++) {
        int v = (base + i < NN) ? g_cntc[base + i] : 0;
        loc[i] = s; s += v;
    }
    ss[t] = s;
    __syncthreads();
    for (int off = 1; off < 1024; off <<= 1) {
        int v = (t >= off) ? ss[t - off] : 0;
        __syncthreads();
        ss[t] += v;
        __syncthreads();
    }
    int pre = (t > 0) ? ss[t - 1] : 0;
#pragma unroll
    for (int i = 0; i < 10; i++)
        if (base + i < NN) g_cptr[base + i] = pre + loc[i];
    if (t == 1023) g_cptr[NN] = ss[1023];
}

__global__ void k_scatter(const int* __restrict__ ei) {
    int e = blockIdx.x * blockDim.x + threadIdx.x;
    if (e < EE) {
        int c = ei[EE + e];
        int p = g_cptr[c] + atomicAdd(&g_fill[c], 1);
        g_ebc[p] = e;
    }
}

// -------- edge MLP: k1 scalar, k2 via tf32 mma with B-frags from L2 ---------------
__global__ __launch_bounds__(256) void k_edge_mma(
    const int* __restrict__ ei, const float* __restrict__ attr,
    const float* __restrict__ W1, const float* __restrict__ B1,
    const float* __restrict__ B2) {
    __shared__ unsigned s_k1[64][36];     // [edge][kk] tf32
    __shared__ float s_kin[64][8];
    __shared__ float s_w1[7 * 64];
    __shared__ float s_b1[64];
    __shared__ float s_b2[128];
    int t = threadIdx.x, warp = t >> 5, lane = t & 31;
    int e0 = blockIdx.x * 64;

    for (int i = t; i < 7 * 64; i += 256) s_w1[i] = W1[i];
    if (t < 64) s_b1[t] = B1[t];
    else if (t < 192) s_b2[t - 64] = B2[t - 64];

    if (t < 64) {
        int e = e0 + t;
        float rad = 0.f;
        if (e < EE) {
            int r = ei[e], c = ei[EE + e];
            float d0 = g_coord[r * 3 + 0] - g_coord[c * 3 + 0];
            float d1 = g_coord[r * 3 + 1] - g_coord[c * 3 + 1];
            float d2 = g_coord[r * 3 + 2] - g_coord[c * 3 + 2];
            rad = d0 * d0 + d1 * d1 + d2 * d2;
#pragma unroll
            for (int q = 0; q < 6; q++) s_kin[t][q] = attr[e * 6 + q];
        } else {
#pragma unroll
            for (int q = 0; q < 6; q++) s_kin[t][q] = 0.f;
        }
        s_kin[t][6] = rad;
        s_kin[t][7] = 0.f;
    }
    __syncthreads();

    int wm = warp & 3, wn = warp >> 2;
    int qr = lane >> 2, qc = lane & 3;
    const uint2* bf = (const uint2*)g_W2f;
    float acc[8][4];
#pragma unroll
    for (int nt = 0; nt < 8; nt++)
#pragma unroll
        for (int j = 0; j < 4; j++) acc[nt][j] = 0.f;

    for (int half = 0; half < 2; half++) {
        for (int i = t; i < 64 * 32; i += 256) {
            int e = i >> 5, cc = i & 31, c = half * 32 + cc;
            float s = s_b1[c];
#pragma unroll
            for (int q = 0; q < 7; q++) s = fmaf(s_kin[e][q], s_w1[q * 64 + c], s);
            s_k1[e][cc] = f2tf32(fmaxf(s, 0.f));
        }
        __syncthreads();

#pragma unroll
        for (int ks = 0; ks < 4; ks++) {
            int k0 = ks * 8;
            unsigned a0 = s_k1[wm * 16 + qr][k0 + qc];
            unsigned a1 = s_k1[wm * 16 + qr + 8][k0 + qc];
            unsigned a2 = s_k1[wm * 16 + qr][k0 + qc + 4];
            unsigned a3 = s_k1[wm * 16 + qr + 8][k0 + qc + 4];
            uint2 bv[8];
#pragma unroll
            for (int nt = 0; nt < 8; nt++)
                bv[nt] = bf[((half * 16 + wn * 8 + nt) * 4 + ks) * 32 + lane];
#pragma unroll
            for (int nt = 0; nt < 8; nt++)
                mma_tf32(acc[nt][0], acc[nt][1], acc[nt][2], acc[nt][3],
                         a0, a1, a2, a3, bv[nt].x, bv[nt].y);
        }
        __syncthreads();
    }

    int eA = e0 + wm * 16 + qr, eB = eA + 8;
#pragma unroll
    for (int nt = 0; nt < 8; nt++) {
        int col = wn * 64 + nt * 8 + 2 * qc;
        float bx = s_b2[col], by = s_b2[col + 1];
        if (eA < EE)
            *(__half2*)&g_k2h[(size_t)eA * 128 + col] =
                __floats2half2_rn(fmaxf(acc[nt][0] + bx, 0.f), fmaxf(acc[nt][1] + by, 0.f));
        if (eB < EE)
            *(__half2*)&g_k2h[(size_t)eB * 128 + col] =
                __floats2half2_rn(fmaxf(acc[nt][2] + bx, 0.f), fmaxf(acc[nt][3] + by, 0.f));
    }
}

// -------- W3h via tf32 mma, 32n x 256o, B-frags streamed from L2 ------------------
__global__ __launch_bounds__(256) void k_w3h_mma() {
    __shared__ __align__(16) char sb[32 * 132 * 4];   // A stage (4.6KB) / epilogue (16.9KB)
    unsigned (*sa)[36] = (unsigned(*)[36])sb;
    int t = threadIdx.x, warp = t >> 5, lane = t & 31;
    int cg = blockIdx.x & 15;
    int n0 = (blockIdx.x >> 4) * 32;

    // stage A: 32 x 32, one float4 per thread
    {
        int n = t >> 3, kq = t & 7;
        float4 v = make_float4(0.f, 0.f, 0.f, 0.f);
        if (n0 + n < NN) v = *(const float4*)&g_h[(n0 + n) * 32 + kq * 4];
        sa[n][kq * 4 + 0] = f2tf32(v.x); sa[n][kq * 4 + 1] = f2tf32(v.y);
        sa[n][kq * 4 + 2] = f2tf32(v.z); sa[n][kq * 4 + 3] = f2tf32(v.w);
    }
    __syncthreads();

    int wm = warp & 1, wn = warp >> 1;   // wm: 16-row group; wn: 64-out group
    int qr = lane >> 2, qc = lane & 3;
    const uint2* bf = (const uint2*)g_W3f + (size_t)cg * 32 * 4 * 32;
    float acc[8][4];
#pragma unroll
    for (int nt = 0; nt < 8; nt++)
#pragma unroll
        for (int j = 0; j < 4; j++) acc[nt][j] = 0.f;

#pragma unroll
    for (int ks = 0; ks < 4; ks++) {
        int k0 = ks * 8;
        unsigned a0 = sa[wm * 16 + qr][k0 + qc];
        unsigned a1 = sa[wm * 16 + qr + 8][k0 + qc];
        unsigned a2 = sa[wm * 16 + qr][k0 + qc + 4];
        unsigned a3 = sa[wm * 16 + qr + 8][k0 + qc + 4];
        uint2 bv[8];
#pragma unroll
        for (int nt = 0; nt < 8; nt++)
            bv[nt] = bf[((wn * 8 + nt) * 4 + ks) * 32 + lane];
#pragma unroll
        for (int nt = 0; nt < 8; nt++)
            mma_tf32(acc[nt][0], acc[nt][1], acc[nt][2], acc[nt][3],
                     a0, a1, a2, a3, bv[nt].x, bv[nt].y);
    }
    __syncthreads();   // A dead; reuse smem as half2 tile (32 rows x 132 words)

    unsigned* so = (unsigned*)sb;
    int nlA = wm * 16 + qr, nlB = nlA + 8;
#pragma unroll
    for (int g = 0; g < 4; g++) {
#pragma unroll
        for (int j = 0; j < 2; j++) {
            int w = g * 32 + (2 * qc + j) * 4 + wn;
            __half2 vA = __floats2half2_rn(acc[g][j], acc[g + 4][j]);
            __half2 vB = __floats2half2_rn(acc[g][2 + j], acc[g + 4][2 + j]);
            so[nlA * 132 + w] = *(unsigned*)&vA;
            so[nlB * 132 + w] = *(unsigned*)&vB;
        }
    }
    __syncthreads();

    int ks = cg >> 1, par = cg & 1;
    for (int r = warp; r < 32; r += 8) {
        int n = n0 + r;
        if (n < NN) {
#pragma unroll
            for (int ch = 0; ch < 4; ch++)
                g_W3hB[(size_t)n * 2048 + ks * 256 + ch * 64 + par * 32 + lane] =
                    so[r * 132 + ch * 32 + lane];
        }
    }
}

// -------- contraction: fp16 mma for m AND phi; lane-parallel epilogue -------------
__global__ __launch_bounds__(128) void k_contract_mma(
    const int* __restrict__ ei, const float* __restrict__ B3,
    const float* __restrict__ CW1, const float* __restrict__ CB1,
    const float* __restrict__ CW2) {
    __shared__ float  s_cw1[32][33];
    __shared__ float  s_b3t[32][33];
    __shared__ float  s_cw2[32];
    __shared__ __half s_a[4][16][136];
    __shared__ float  s_m[4][16][33];
    __shared__ float  s_p[4][16][33];
    __shared__ float  s_bt[4][32];
    __shared__ float  s_cc[4][4];
    __shared__ int    s_e[4][16];
    __shared__ int    s_rn[4][16];
    int t = threadIdx.x, lane = t & 31, w = t >> 5;
    for (int i = t; i < 1024; i += 128) {
        s_cw1[i >> 5][i & 31] = CW1[i];
        s_b3t[i & 31][i >> 5] = B3[i];
    }
    if (t < 32) s_cw2[t] = CW2[t];
    __syncthreads();

    int n = blockIdx.x * 4 + w;
    if (n >= NN) return;
    int beg = g_cptr[n], end = g_cptr[n + 1];
    if (beg == end) return;

    int qr = lane >> 2, qc = lane & 3;

    unsigned u[64];
    const unsigned* bp = g_W3hB + (size_t)n * 2048 + lane;
#pragma unroll
    for (int f = 0; f < 64; f++) u[f] = bp[f * 32];

    unsigned ucw[2][4][2];
#pragma unroll
    for (int ks2 = 0; ks2 < 2; ks2++)
#pragma unroll
        for (int nt = 0; nt < 4; nt++) {
            int kb = ks2 * 16 + 2 * qc, nb = nt * 8 + qr;
            ucw[ks2][nt][0] = packh2(s_cw1[kb][nb], s_cw1[kb + 1][nb]);
            ucw[ks2][nt][1] = packh2(s_cw1[kb + 8][nb], s_cw1[kb + 9][nb]);
        }

    float hv = g_h[n * 32 + lane];
    float bh = 0.f;
#pragma unroll
    for (int j = 0; j < 32; j++)
        bh = fmaf(s_b3t[j][lane], __shfl_sync(0xffffffffu, hv, j), bh);
    float bterm = CB1[lane];
#pragma unroll
    for (int j = 0; j < 32; j++)
        bterm = fmaf(__shfl_sync(0xffffffffu, bh, j), s_cw1[j][lane], bterm);
    s_bt[w][lane] = bterm;
    if (lane < 3) s_cc[w][lane] = g_coord[n * 3 + lane];
    __syncwarp();

    for (int g0 = beg; g0 < end; g0 += 16) {
        int gsz = min(16, end - g0);
        if (lane < 16) {
            int e = (lane < gsz) ? g_ebc[g0 + lane] : g_ebc[g0];
            s_e[w][lane] = e;
            s_rn[w][lane] = ei[e];
        }
        __syncwarp();
#pragma unroll
        for (int it = 0; it < 8; it++) {
            int idx = it * 32 + lane;
            int row = idx >> 4, part = idx & 15;
            ((uint4*)&s_a[w][row][0])[part] =
                ((const uint4*)(g_k2h + (size_t)s_e[w][row] * 128))[part];
        }
        __syncwarp();

        float acc[4][4];
#pragma unroll
        for (int nt = 0; nt < 4; nt++)
#pragma unroll
            for (int j = 0; j < 4; j++) acc[nt][j] = 0.f;

#pragma unroll
        for (int ks = 0; ks < 8; ks++) {
            int k0 = ks * 16 + 2 * qc;
            unsigned a0 = *(const unsigned*)&s_a[w][qr][k0];
            unsigned a1 = *(const unsigned*)&s_a[w][qr + 8][k0];
            unsigned a2 = *(const unsigned*)&s_a[w][qr][k0 + 8];
            unsigned a3 = *(const unsigned*)&s_a[w][qr + 8][k0 + 8];
#pragma unroll
            for (int nt = 0; nt < 4; nt++)
                mma_f16(acc[nt][0], acc[nt][1], acc[nt][2], acc[nt][3],
                        a0, a1, a2, a3, u[(ks * 4 + nt) * 2], u[(ks * 4 + nt) * 2 + 1]);
        }
        __syncwarp();
#pragma unroll
        for (int nt = 0; nt < 4; nt++) {
#pragma unroll
            for (int j = 0; j < 2; j++) {
                s_m[w][qr][nt * 8 + 2 * qc + j] = acc[nt][j];
                s_m[w][qr + 8][nt * 8 + 2 * qc + j] = acc[nt][2 + j];
            }
        }
        __syncwarp();

        float pacc[4][4];
#pragma unroll
        for (int nt = 0; nt < 4; nt++)
#pragma unroll
            for (int j = 0; j < 4; j++) pacc[nt][j] = 0.f;
#pragma unroll
        for (int ks2 = 0; ks2 < 2; ks2++) {
            int kb = ks2 * 16 + 2 * qc;
            unsigned a0 = packh2(s_m[w][qr][kb], s_m[w][qr][kb + 1]);
            unsigned a1 = packh2(s_m[w][qr + 8][kb], s_m[w][qr + 8][kb + 1]);
            unsigned a2 = packh2(s_m[w][qr][kb + 8], s_m[w][qr][kb + 9]);
            unsigned a3 = packh2(s_m[w][qr + 8][kb + 8], s_m[w][qr + 8][kb + 9]);
#pragma unroll
            for (int nt = 0; nt < 4; nt++)
                mma_f16(pacc[nt][0], pacc[nt][1], pacc[nt][2], pacc[nt][3],
                        a0, a1, a2, a3, ucw[ks2][nt][0], ucw[ks2][nt][1]);
        }
#pragma unroll
        for (int nt = 0; nt < 4; nt++) {
#pragma unroll
            for (int j = 0; j < 2; j++) {
                s_p[w][qr][nt * 8 + 2 * qc + j] = pacc[nt][j];
                s_p[w][qr + 8][nt * 8 + 2 * qc + j] = pacc[nt][2 + j];
            }
        }
        __syncwarp();

        int rr = lane & 15;
        float tj = 0.f;
#pragma unroll
        for (int i = 0; i < 32; i++)
            tj = fmaf(fmaxf(s_p[w][rr][i] + s_bt[w][i], 0.f), s_cw2[i], tj);
        if (lane < gsz) {
            int rn = s_rn[w][lane];
#pragma unroll
            for (int k = 0; k < 3; k++)
                atomicAdd(&g_accc[rn * 3 + k],
                          (g_coord[rn * 3 + k] - s_cc[w][k]) * tj);
        }

        for (int r = 0; r < gsz; r++) {
            int rn = s_rn[w][r];
            float mi = s_m[w][r][lane] + bh;
            atomicAdd(&g_acch[rn * 32 + lane], mi);
        }
        __syncwarp();
    }
}

// ---------------- node update (invc inlined) --------------------------------------
__global__ void k_update() {
    int idx = blockIdx.x * blockDim.x + threadIdx.x;
    if (idx >= NN * 32) return;
    int n = idx >> 5, j = idx & 31;
    int c = g_cntr[n];
    float inv = 1.f / (float)(c > 0 ? c : 1);
    g_h[idx] = fmaxf(g_h[idx] + g_acch[idx] * inv, 0.f);
    g_acch[idx] = 0.f;
    if (j < 3) {
        g_coord[n * 3 + j] += g_accc[n * 3 + j] * inv;
        g_accc[n * 3 + j] = 0.f;
    }
}

// ---------------- final MLP + coord copy ------------------------------------------
__global__ void k_final(const float* __restrict__ w1, const float* __restrict__ b1,
                        const float* __restrict__ w2, const float* __restrict__ b2,
                        float* __restrict__ out) {
    int gid = blockIdx.x * blockDim.x + threadIdx.x;
    if (gid < NN * 3) out[NN + gid] = g_coord[gid];
    int lane = gid & 31;
    int n = gid >> 5;
    if (n >= NN) return;
    float hv = g_h[n * 32 + lane];
    float t0 = b1[lane], t1 = b1[32 + lane];
#pragma unroll
    for (int j = 0; j < 32; j++) {
        float hj = __shfl_sync(0xffffffffu, hv, j);
        t0 = fmaf(hj, w1[j * 64 + lane], t0);
        t1 = fmaf(hj, w1[j * 64 + 32 + lane], t1);
    }
    float s = fmaxf(t0, 0.f) * w2[lane] + fmaxf(t1, 0.f) * w2[32 + lane];
#pragma unroll
    for (int o = 16; o; o >>= 1) s += __shfl_xor_sync(0xffffffffu, s, o);
    if (lane == 0) out[n] = s + b2[0];
}

// ---------------------------------------------------------------------------------
extern "C" void kernel_launch(void* const* d_in, const int* in_sizes, int n_in,
                              void* d_out, int out_size) {
    const float* x    = (const float*)d_in[0];
    const int*   ei   = (const int*)d_in[1];
    const float* attr = (const float*)d_in[2];
    const float* ci   = (const float*)d_in[3];
    const float* f1w  = (const float*)d_in[4];
    const float* f1b  = (const float*)d_in[5];
    const float* kw1  = (const float*)d_in[6];
    const float* kb1  = (const float*)d_in[7];
    const float* kw2  = (const float*)d_in[8];
    const float* kb2  = (const float*)d_in[9];
    const float* kw3  = (const float*)d_in[10];
    const float* kb3  = (const float*)d_in[11];
    const float* cw1  = (const float*)d_in[12];
    const float* cb1  = (const float*)d_in[13];
    const float* cw2  = (const float*)d_in[14];
    const float* f2w1 = (const float*)d_in[15];
    const float* f2b1 = (const float*)d_in[16];
    const float* f2w2 = (const float*)d_in[17];
    const float* f2b2 = (const float*)d_in[18];
    float* out = (float*)d_out;

    int w3h_grid = ((NN + 31) / 32) * 16;
    int edge_grid = (EE + 63) / 64;

    k_pack<<<(131072 + 255) / 256, 256>>>(kw3, kw2);                    // 0
    k_prep<<<(NN * 32 + 255) / 256, 256>>>(x, f1w, f1b, ci);            // 1
    k_hist<<<(EE + 255) / 256, 256>>>(ei);                               // 2
    k_w3h_mma<<<w3h_grid, 256>>>();                                      // 3 <- profiled
    k_scan<<<1, 1024>>>();                                               // 4
    k_scatter<<<(EE + 255) / 256, 256>>>(ei);                            // 5
    k_edge_mma<<<edge_grid, 256>>>(ei, attr, kw1, kb1, kb2);             // 6 (L0)
    k_contract_mma<<<(NN + 3) / 4, 128>>>(ei, kb3, cw1, cb1, cw2);       // 7 (L0)
    k_update<<<(NN * 32 + 255) / 256, 256>>>();                          // 8 (L0)

    for (int L = 1; L < 3; L++) {
        k_edge_mma<<<edge_grid, 256>>>(ei, attr, kw1, kb1, kb2);
        k_w3h_mma<<<w3h_grid, 256>>>();
        k_contract_mma<<<(NN + 3) / 4, 128>>>(ei, kb3, cw1, cb1, cw2);
        k_update<<<(NN * 32 + 255) / 256, 256>>>();
    }

    k_final<<<(NN * 32 + 255) / 256, 256>>>(f2w1, f2b1, f2w2, f2b2, out);
}